// round 2
// baseline (speedup 1.0000x reference)
#include <cuda_runtime.h>
#include <math.h>

#define EPS 1e-8f
#define B_   32
#define CPD_ 32
#define F_   1024
#define D_   1024
#define S_   128
#define BF_  (B_*F_)        // 32768

// ---------------- device scratch (no runtime allocation allowed) ----------------
__device__ float g_WD[CPD_*D_];        // W @ direct   [32][1024]
__device__ float g_WB[CPD_*S_];        // W @ input    [32][128]
__device__ float g_G[CPD_*CPD_];       // W @ W^T      [32][32]
__device__ float g_yd[(size_t)BF_*D_]; // scaled d rows, layout [f*32+b][1024]
__device__ float g_yb[(size_t)BF_*S_]; // scaled b rows, layout [f*32+b][128]
__device__ float g_sp[(size_t)BF_*S_]; // s'_t rows,     layout [t*32+b][128]
__device__ float g_nsp[BF_];           // ||s'_t||
__device__ float g_xc[(size_t)BF_*D_]; // unscaled c GEMM out [t*32+b][1024]
__device__ float g_cs2[BF_];           // row sumsq of g_xc (atomic)
__device__ float g_fc[BF_];            // c factor

// ---------------- zero atomic accumulators (every replay) ----------------
__global__ void k_zero() {
    int i = blockIdx.x * 256 + threadIdx.x;
    if (i < BF_) g_cs2[i] = 0.f;
    if (i < CPD_*CPD_) g_G[i] = 0.f;
}

// ---------------- WD = W @ direct ----------------
__global__ void k_wd(const float* __restrict__ W, const float* __restrict__ Dm) {
    int gid = blockIdx.x * 256 + threadIdx.x;
    if (gid >= CPD_ * D_) return;
    int i = gid >> 10, j = gid & 1023;
    const float* wr = W + i * 1024;
    float acc = 0.f;
#pragma unroll 8
    for (int k = 0; k < 1024; k++) acc += wr[k] * Dm[k * D_ + j];
    g_WD[gid] = acc;
}

// ---------------- WB = W @ input ----------------
__global__ void k_wb(const float* __restrict__ W, const float* __restrict__ In) {
    int gid = blockIdx.x * 256 + threadIdx.x;
    if (gid >= CPD_ * S_) return;
    int i = gid >> 7, j = gid & 127;
    const float* wr = W + i * 1024;
    float acc = 0.f;
#pragma unroll 8
    for (int k = 0; k < 1024; k++) acc += wr[k] * In[k * S_ + j];
    g_WB[gid] = acc;
}

// ---------------- G = W @ W^T, k-split, atomics into zeroed g_G ----------------
__global__ void k_gram(const float* __restrict__ W) {
    __shared__ float Wt[64 * 33];
    int k0 = blockIdx.x * 64;
    int tid = threadIdx.x;
    for (int lin = tid; lin < 2048; lin += 256) {
        int i = lin >> 6, kk = lin & 63;
        Wt[kk * 33 + i] = W[i * 1024 + k0 + kk];
    }
    __syncthreads();
#pragma unroll
    for (int q = 0; q < 4; q++) {
        int o = tid * 4 + q;
        int i = o >> 5, i2 = o & 31;
        float acc = 0.f;
#pragma unroll 8
        for (int kk = 0; kk < 64; kk++) acc += Wt[kk * 33 + i] * Wt[kk * 33 + i2];
        atomicAdd(&g_G[o], acc);
    }
}

__device__ __forceinline__ float warp_sum(float v) {
#pragma unroll
    for (int m = 16; m > 0; m >>= 1) v += __shfl_xor_sync(0xffffffffu, v, m);
    return v;
}

// ---------------- fused per-row: yd, yb with all factors ----------------
// 256 threads; WD held in registers (128/thread), WB + G in shared.
__global__ __launch_bounds__(256) void k_rows(const float* __restrict__ control) {
    __shared__ float WBs[CPD_ * S_];   // 16KB
    __shared__ float Gs[CPD_ * CPD_];  // 4KB
    __shared__ float c_sh[CPD_];
    __shared__ float red_sd[8], red_sb[8];
    __shared__ float s_nv2, s_nx2;
    __shared__ float s_fd, s_fb;

    int tid = threadIdx.x;
    int warp = tid >> 5, lane = tid & 31;

    // load WB, G to shared
    for (int i = tid; i < CPD_ * S_; i += 256) WBs[i] = g_WB[i];
    for (int i = tid; i < CPD_ * CPD_; i += 256) Gs[i] = g_G[i];

    // load this thread's WD columns {tid, tid+256, tid+512, tid+768}
    float wdr[4][32];
#pragma unroll
    for (int jj = 0; jj < 4; jj++)
#pragma unroll
        for (int i = 0; i < 32; i++)
            wdr[jj][i] = g_WD[i * 1024 + jj * 256 + tid];
    __syncthreads();

    for (int r = blockIdx.x; r < BF_; r += gridDim.x) {
        int f = r >> 5, b = r & 31;
        if (tid < 32) c_sh[tid] = control[(size_t)b * (CPD_ * F_) + tid * F_ + f];
        __syncthreads();

        // warp0: nv2, nx2 = c^T G c
        if (warp == 0) {
            float ci = c_sh[lane];
            float gd = 0.f;
#pragma unroll
            for (int k = 0; k < 32; k++) gd += Gs[lane * 32 + k] * c_sh[k];
            float nv2 = warp_sum(ci * ci);
            float nx2 = warp_sum(ci * gd);
            if (lane == 0) { s_nv2 = nv2; s_nx2 = nx2; }
        }

        // yd: 4 columns per thread
        float yd0 = 0.f, yd1 = 0.f, yd2 = 0.f, yd3 = 0.f;
#pragma unroll
        for (int i = 0; i < 32; i++) {
            float ci = c_sh[i];
            yd0 += wdr[0][i] * ci;
            yd1 += wdr[1][i] * ci;
            yd2 += wdr[2][i] * ci;
            yd3 += wdr[3][i] * ci;
        }
        // yb: threads < 128, 1 column each
        float yb = 0.f;
        if (tid < 128) {
#pragma unroll
            for (int i = 0; i < 32; i++) yb += WBs[i * 128 + tid] * c_sh[i];
        }

        float sd = yd0 * yd0 + yd1 * yd1 + yd2 * yd2 + yd3 * yd3;
        float sb = (tid < 128) ? yb * yb : 0.f;
        sd = warp_sum(sd);
        sb = warp_sum(sb);
        if (lane == 0) { red_sd[warp] = sd; red_sb[warp] = sb; }
        __syncthreads();

        if (tid == 0) {
            float tsd = 0.f, tsb = 0.f;
#pragma unroll
            for (int w = 0; w < 8; w++) { tsd += red_sd[w]; tsb += red_sb[w]; }
            float nv = sqrtf(s_nv2), nx = sqrtf(s_nx2);
            float facp = fminf(nx, nv) / (nx + EPS);
            float nproj = facp * nx;
            float nxd = facp * sqrtf(tsd);
            float nxb = facp * sqrtf(tsb);
            s_fd = facp * (fminf(nxd, nproj) / (nxd + EPS));
            s_fb = facp * (fminf(nxb, nproj) / (nxb + EPS));
        }
        __syncthreads();

        float fd = s_fd, fb = s_fb;
        size_t base = (size_t)r * 1024;
        g_yd[base + 0 * 256 + tid] = fd * yd0;
        g_yd[base + 1 * 256 + tid] = fd * yd1;
        g_yd[base + 2 * 256 + tid] = fd * yd2;
        g_yd[base + 3 * 256 + tid] = fd * yd3;
        if (tid < 128) g_yb[(size_t)r * 128 + tid] = fb * yb;
    }
}

// ---------------- sequential scan: one block per batch ----------------
// 512 threads: q = tid>>7 in 0..3 (k-quarter), j = tid&127 (state element)
__global__ __launch_bounds__(512) void k_scan(const float* __restrict__ A) {
    __shared__ float s_sh[S_];
    __shared__ float xred[512];
    __shared__ float red1[4], red2[4];
    __shared__ float s_fac;

    int b = blockIdx.x;
    int tid = threadIdx.x;
    int q = tid >> 7, j = tid & 127;
    int warp = tid >> 5, lane = tid & 31;

    float a[32];
#pragma unroll
    for (int kk = 0; kk < 32; kk++) a[kk] = A[(q * 32 + kk) * 128 + j];

    if (tid < 128) s_sh[tid] = 0.f;
    float ns2 = 0.f;  // meaningful on thread 0 only
    __syncthreads();

    for (int t = 0; t < F_; t++) {
        // partial matvec
        float a0 = 0.f, a1 = 0.f, a2 = 0.f, a3 = 0.f;
#pragma unroll
        for (int kk = 0; kk < 32; kk += 4) {
            a0 += a[kk + 0] * s_sh[q * 32 + kk + 0];
            a1 += a[kk + 1] * s_sh[q * 32 + kk + 1];
            a2 += a[kk + 2] * s_sh[q * 32 + kk + 2];
            a3 += a[kk + 3] * s_sh[q * 32 + kk + 3];
        }
        xred[tid] = (a0 + a1) + (a2 + a3);
        __syncthreads();  // #1

        float xs = 0.f, binp = 0.f;
        if (tid < 128) {
            xs = xred[j] + xred[128 + j] + xred[256 + j] + xred[384 + j];
            binp = g_yb[(size_t)(t * 32 + b) * 128 + j];
            float p = warp_sum(xs * xs);
            if (lane == 0) red1[warp] = p;
        }
        __syncthreads();  // #2

        if (tid == 0) {
            float nxs2 = red1[0] + red1[1] + red1[2] + red1[3];
            float nxs = sqrtf(nxs2);
            float ns = sqrtf(ns2);
            float fac = fminf(nxs, ns) / (nxs + EPS);
            s_fac = fac;
            g_nsp[t * 32 + b] = nxs * fac;
        }
        __syncthreads();  // #3

        if (tid < 128) {
            float fac = s_fac;
            float sp = fac * xs;
            g_sp[(size_t)(t * 32 + b) * 128 + j] = sp;
            float snew = sp + binp;
            s_sh[j] = snew;
            float p2 = warp_sum(snew * snew);
            if (lane == 0) red2[warp] = p2;
        }
        __syncthreads();  // #4

        if (tid == 0) ns2 = red2[0] + red2[1] + red2[2] + red2[3];
    }
}

// ---------------- XC = Sprime[32768,128] @ output_matrix[128,1024] ----------------
#define KC 32
__global__ __launch_bounds__(256) void k_gemm(const float* __restrict__ Bm) {
    __shared__ float As[KC][128];
    __shared__ float Bs[KC][128];
    __shared__ float rowred[128];

    int m0 = blockIdx.y * 128, n0 = blockIdx.x * 128;
    int tid = threadIdx.x;
    int tm = tid >> 4, tn = tid & 15;

    float acc[8][8];
#pragma unroll
    for (int i = 0; i < 8; i++)
#pragma unroll
        for (int k = 0; k < 8; k++) acc[i][k] = 0.f;
    if (tid < 128) rowred[tid] = 0.f;

    const float4* A4 = (const float4*)g_sp;
    const float4* B4 = (const float4*)Bm;

    for (int kc = 0; kc < 128; kc += KC) {
        __syncthreads();
#pragma unroll
        for (int ii = 0; ii < 4; ii++) {
            int slot = tid + ii * 256;       // 0..1023
            int m = slot >> 3, k4 = slot & 7;
            float4 v = A4[(size_t)(m0 + m) * 32 + (kc >> 2) + k4];
            As[k4 * 4 + 0][m] = v.x;
            As[k4 * 4 + 1][m] = v.y;
            As[k4 * 4 + 2][m] = v.z;
            As[k4 * 4 + 3][m] = v.w;
        }
#pragma unroll
        for (int ii = 0; ii < 4; ii++) {
            int slot = tid + ii * 256;
            int k = slot >> 5, n4 = slot & 31;
            float4 v = B4[(size_t)(kc + k) * 256 + (n0 >> 2) + n4];
            *((float4*)&Bs[k][n4 * 4]) = v;
        }
        __syncthreads();
#pragma unroll
        for (int k = 0; k < KC; k++) {
            float af[8], bf[8];
#pragma unroll
            for (int x = 0; x < 8; x++) af[x] = As[k][tm * 8 + x];
#pragma unroll
            for (int x = 0; x < 8; x++) bf[x] = Bs[k][tn * 8 + x];
#pragma unroll
            for (int mi = 0; mi < 8; mi++)
#pragma unroll
                for (int ni = 0; ni < 8; ni++) acc[mi][ni] += af[mi] * bf[ni];
        }
    }

    // epilogue: store tile + per-row sumsq
#pragma unroll
    for (int mi = 0; mi < 8; mi++) {
        int row = m0 + tm * 8 + mi;
        float rs = 0.f;
#pragma unroll
        for (int ni = 0; ni < 8; ni++) rs += acc[mi][ni] * acc[mi][ni];
        float4 v0 = make_float4(acc[mi][0], acc[mi][1], acc[mi][2], acc[mi][3]);
        float4 v1 = make_float4(acc[mi][4], acc[mi][5], acc[mi][6], acc[mi][7]);
        float4* dst = (float4*)&g_xc[(size_t)row * 1024 + n0 + tn * 8];
        dst[0] = v0;
        dst[1] = v1;
        atomicAdd(&rowred[tm * 8 + mi], rs);
    }
    __syncthreads();
    if (tid < 128) atomicAdd(&g_cs2[m0 + tid], rowred[tid]);
}

// ---------------- c factors ----------------
__global__ void k_fc() {
    int r = blockIdx.x * 256 + threadIdx.x;
    if (r >= BF_) return;
    float nxc = sqrtf(g_cs2[r]);
    float nsp = g_nsp[r];
    g_fc[r] = fminf(nxc, nsp) / (nxc + EPS);
}

// ---------------- window + overlap-add ----------------
__global__ void k_ola(float* __restrict__ out) {
    size_t idx = (size_t)blockIdx.x * 256 + threadIdx.x;  // 32 * 524288 total
    int b = (int)(idx >> 19);
    int i = (int)(idx & 524287);
    int f1 = i >> 9, j1 = i & 511;
    float c = cosf((float)j1 * 6.2831853071795864769e0f / 1024.0f);
    float w1 = 0.5f * (1.0f - c);
    float w0 = 0.5f * (1.0f + c);
    int r1 = (f1 << 5) + b;
    float v = (g_fc[r1] * g_xc[(size_t)r1 * 1024 + j1] + g_yd[(size_t)r1 * 1024 + j1]) * w1;
    if (f1 > 0) {
        int r0 = r1 - 32;
        int j0 = j1 + 512;
        v += (g_fc[r0] * g_xc[(size_t)r0 * 1024 + j0] + g_yd[(size_t)r0 * 1024 + j0]) * w0;
    }
    out[idx] = v;
}

extern "C" void kernel_launch(void* const* d_in, const int* in_sizes, int n_in,
                              void* d_out, int out_size) {
    const float* control  = (const float*)d_in[0];
    const float* proj_w   = (const float*)d_in[1];
    const float* state_m  = (const float*)d_in[2];
    const float* input_m  = (const float*)d_in[3];
    const float* output_m = (const float*)d_in[4];
    const float* direct_m = (const float*)d_in[5];
    float* out = (float*)d_out;

    k_zero<<<132, 256>>>();
    k_wd<<<128, 256>>>(proj_w, direct_m);
    k_wb<<<16, 256>>>(proj_w, input_m);
    k_gram<<<16, 256>>>(proj_w);
    k_rows<<<148, 256>>>(control);
    k_scan<<<32, 512>>>(state_m);
    k_gemm<<<dim3(8, 256), 256>>>(output_m);
    k_fc<<<128, 256>>>();
    k_ola<<<65536, 256>>>(out);
}

// round 4
// speedup vs baseline: 1.0947x; 1.0947x over previous
#include <cuda_runtime.h>
#include <math.h>

#define EPS 1e-8f
#define B_   32
#define CPD_ 32
#define F_   1024
#define D_   1024
#define S_   128
#define BF_  (B_*F_)        // 32768

// ---------------- device scratch (no runtime allocation allowed) ----------------
__device__ float g_WD[CPD_*D_];        // W @ direct   [32][1024]
__device__ float g_WB[CPD_*S_];        // W @ input    [32][128]
__device__ float g_G[CPD_*CPD_];       // W @ W^T      [32][32]
__device__ float g_yd[(size_t)BF_*D_]; // scaled d rows, layout [f*32+b][1024]
__device__ float g_yb[(size_t)BF_*S_]; // scaled b rows, layout [f*32+b][128]
__device__ float g_sp[(size_t)BF_*S_]; // s'_t rows,     layout [t*32+b][128]
__device__ float g_nsp[BF_];           // ||s'_t||
__device__ float g_xc[(size_t)BF_*D_]; // unscaled c GEMM out [t*32+b][1024]
__device__ float g_cs2[BF_];           // row sumsq of g_xc (atomic)
__device__ float g_fc[BF_];            // c factor

__device__ __forceinline__ float warp_sum(float v) {
#pragma unroll
    for (int m = 16; m > 0; m >>= 1) v += __shfl_xor_sync(0xffffffffu, v, m);
    return v;
}

// ---------------- zero atomic accumulators (every replay) ----------------
__global__ void k_zero() {
    int i = blockIdx.x * 256 + threadIdx.x;
    if (i < BF_) g_cs2[i] = 0.f;
    if (i < CPD_*CPD_) g_G[i] = 0.f;
}

// ---------------- WD = W @ direct ----------------
__global__ void k_wd(const float* __restrict__ W, const float* __restrict__ Dm) {
    int gid = blockIdx.x * 256 + threadIdx.x;
    if (gid >= CPD_ * D_) return;
    int i = gid >> 10, j = gid & 1023;
    const float* wr = W + i * 1024;
    float acc = 0.f;
#pragma unroll 8
    for (int k = 0; k < 1024; k++) acc += wr[k] * Dm[k * D_ + j];
    g_WD[gid] = acc;
}

// ---------------- WB = W @ input ----------------
__global__ void k_wb(const float* __restrict__ W, const float* __restrict__ In) {
    int gid = blockIdx.x * 256 + threadIdx.x;
    if (gid >= CPD_ * S_) return;
    int i = gid >> 7, j = gid & 127;
    const float* wr = W + i * 1024;
    float acc = 0.f;
#pragma unroll 8
    for (int k = 0; k < 1024; k++) acc += wr[k] * In[k * S_ + j];
    g_WB[gid] = acc;
}

// ---------------- G = W @ W^T, k-split, atomics into zeroed g_G ----------------
__global__ void k_gram(const float* __restrict__ W) {
    __shared__ float Wt[64 * 33];
    int k0 = blockIdx.x * 64;
    int tid = threadIdx.x;
    for (int lin = tid; lin < 2048; lin += 256) {
        int i = lin >> 6, kk = lin & 63;
        Wt[kk * 33 + i] = W[i * 1024 + k0 + kk];
    }
    __syncthreads();
#pragma unroll
    for (int q = 0; q < 4; q++) {
        int o = tid * 4 + q;
        int i = o >> 5, i2 = o & 31;
        float acc = 0.f;
#pragma unroll 8
        for (int kk = 0; kk < 64; kk++) acc += Wt[kk * 33 + i] * Wt[kk * 33 + i2];
        atomicAdd(&g_G[o], acc);
    }
}

// ---------------- fused per-row: yd, yb with all factors ----------------
// 256 threads; WD held in registers (128/thread), WB + G in shared.
// 2 barriers per row: factor math replicated across all threads.
__global__ __launch_bounds__(256) void k_rows(const float* __restrict__ control) {
    __shared__ float WBs[CPD_ * S_];   // 16KB
    __shared__ float Gs[CPD_ * CPD_];  // 4KB
    __shared__ float c_sh[CPD_];
    __shared__ float red_sd[8], red_sb[8];
    __shared__ float s_nv2, s_nx2;

    int tid = threadIdx.x;
    int warp = tid >> 5, lane = tid & 31;

    for (int i = tid; i < CPD_ * S_; i += 256) WBs[i] = g_WB[i];
    for (int i = tid; i < CPD_ * CPD_; i += 256) Gs[i] = g_G[i];

    // this thread's WD columns {tid, tid+256, tid+512, tid+768}
    float wdr[4][32];
#pragma unroll
    for (int jj = 0; jj < 4; jj++)
#pragma unroll
        for (int i = 0; i < 32; i++)
            wdr[jj][i] = g_WD[i * 1024 + jj * 256 + tid];
    __syncthreads();

    for (int r = blockIdx.x; r < BF_; r += gridDim.x) {
        int f = r >> 5, b = r & 31;
        if (tid < 32) c_sh[tid] = control[(size_t)b * (CPD_ * F_) + tid * F_ + f];
        __syncthreads();  // #1: c_sh visible

        // warp0: nv2, nx2 = c^T G c
        if (warp == 0) {
            float ci = c_sh[lane];
            float gd = 0.f;
#pragma unroll
            for (int k = 0; k < 32; k++) gd += Gs[lane * 32 + k] * c_sh[k];
            float nv2 = warp_sum(ci * ci);
            float nx2 = warp_sum(ci * gd);
            if (lane == 0) { s_nv2 = nv2; s_nx2 = nx2; }
        }

        // yd: 4 columns per thread
        float yd0 = 0.f, yd1 = 0.f, yd2 = 0.f, yd3 = 0.f;
#pragma unroll
        for (int i = 0; i < 32; i++) {
            float ci = c_sh[i];
            yd0 += wdr[0][i] * ci;
            yd1 += wdr[1][i] * ci;
            yd2 += wdr[2][i] * ci;
            yd3 += wdr[3][i] * ci;
        }
        // yb: threads < 128, 1 column each
        float yb = 0.f;
        if (tid < 128) {
#pragma unroll
            for (int i = 0; i < 32; i++) yb += WBs[i * 128 + tid] * c_sh[i];
        }

        float sd = warp_sum(yd0 * yd0 + yd1 * yd1 + yd2 * yd2 + yd3 * yd3);
        float sb = warp_sum((tid < 128) ? yb * yb : 0.f);
        if (lane == 0) { red_sd[warp] = sd; red_sb[warp] = sb; }
        __syncthreads();  // #2: red arrays + s_nv2/s_nx2 visible

        // replicated factor computation (no thread-0 serialization, no 3rd bar)
        float tsd = 0.f, tsb = 0.f;
#pragma unroll
        for (int w = 0; w < 8; w++) { tsd += red_sd[w]; tsb += red_sb[w]; }
        float nv = sqrtf(s_nv2), nx = sqrtf(s_nx2);
        float facp = fminf(nx, nv) / (nx + EPS);
        float nproj = facp * nx;
        float nxd = facp * sqrtf(tsd);
        float nxb = facp * sqrtf(tsb);
        float fd = facp * (fminf(nxd, nproj) / (nxd + EPS));
        float fb = facp * (fminf(nxb, nproj) / (nxb + EPS));

        size_t base = (size_t)r * 1024;
        g_yd[base + 0 * 256 + tid] = fd * yd0;
        g_yd[base + 1 * 256 + tid] = fd * yd1;
        g_yd[base + 2 * 256 + tid] = fd * yd2;
        g_yd[base + 3 * 256 + tid] = fd * yd3;
        if (tid < 128) g_yb[(size_t)r * 128 + tid] = fb * yb;
    }
}

// ---------------- sequential scan: one block per batch ----------------
// 512 threads: q = tid>>7 (k-quarter), j = tid&127 (state element)
// 3 barriers/step, shuffle reductions, replicated factor, yb prefetch.
__global__ __launch_bounds__(512) void k_scan(const float* __restrict__ A) {
    __shared__ float s_sh[S_];
    __shared__ float part[512];
    __shared__ float sq[4];     // ||s_t||^2 partials (per warp of lower 128)
    __shared__ float red1[4];   // ||x||^2 partials

    int b = blockIdx.x;
    int tid = threadIdx.x;
    int q = tid >> 7, j = tid & 127;
    int warp = tid >> 5, lane = tid & 31;

    float a[32];
#pragma unroll
    for (int kk = 0; kk < 32; kk++) a[kk] = A[(q * 32 + kk) * 128 + j];

    if (tid < 128) s_sh[tid] = 0.f;
    if (tid < 4) sq[tid] = 0.f;
    float snew = 0.f;      // this thread's state element (tid<128)
    float binp_cur = 0.f, binp_nxt = 0.f;
    if (tid < 128) binp_cur = g_yb[(size_t)b * 128 + j];  // t=0 frame
    __syncthreads();

    for (int t = 0; t < F_; t++) {
        // prefetch next frame's b input (off the critical chain)
        if (tid < 128 && t + 1 < F_)
            binp_nxt = g_yb[(size_t)((t + 1) * 32 + b) * 128 + j];

        // partial matvec over this quarter of k, plus ||s_t||^2 partials
        float a0 = 0.f, a1 = 0.f, a2 = 0.f, a3 = 0.f;
#pragma unroll
        for (int kk = 0; kk < 32; kk += 4) {
            a0 += a[kk + 0] * s_sh[q * 32 + kk + 0];
            a1 += a[kk + 1] * s_sh[q * 32 + kk + 1];
            a2 += a[kk + 2] * s_sh[q * 32 + kk + 2];
            a3 += a[kk + 3] * s_sh[q * 32 + kk + 3];
        }
        part[tid] = (a0 + a1) + (a2 + a3);
        if (tid < 128) {
            float p = warp_sum(snew * snew);   // snew == s_t[j]
            if (lane == 0) sq[warp] = p;
        }
        __syncthreads();  // #1

        float xs = 0.f;
        if (tid < 128) {
            xs = part[j] + part[128 + j] + part[256 + j] + part[384 + j];
            float px = warp_sum(xs * xs);
            if (lane == 0) red1[warp] = px;
        }
        __syncthreads();  // #2

        if (tid < 128) {
            float nxs2 = (red1[0] + red1[1]) + (red1[2] + red1[3]);
            float ns2  = (sq[0] + sq[1]) + (sq[2] + sq[3]);
            float nxs = sqrtf(nxs2);
            float fac = fminf(nxs, sqrtf(ns2)) / (nxs + EPS);
            float sp = fac * xs;
            g_sp[(size_t)(t * 32 + b) * 128 + j] = sp;
            if (tid == 0) g_nsp[t * 32 + b] = fac * nxs;
            snew = sp + binp_cur;
            s_sh[j] = snew;
            binp_cur = binp_nxt;
        }
        __syncthreads();  // #3: s_sh(t+1) visible before next matvec
    }
}

// ---------------- XC = Sprime[32768,128] @ output_matrix[128,1024] ----------------
#define KC 32
__global__ __launch_bounds__(256) void k_gemm(const float* __restrict__ Bm) {
    __shared__ float As[KC][128];
    __shared__ float Bs[KC][128];
    __shared__ float rowred[128];

    int m0 = blockIdx.y * 128, n0 = blockIdx.x * 128;
    int tid = threadIdx.x;
    int tm = tid >> 4, tn = tid & 15;

    float acc[8][8];
#pragma unroll
    for (int i = 0; i < 8; i++)
#pragma unroll
        for (int k = 0; k < 8; k++) acc[i][k] = 0.f;
    if (tid < 128) rowred[tid] = 0.f;

    const float4* A4 = (const float4*)g_sp;
    const float4* B4 = (const float4*)Bm;

    for (int kc = 0; kc < 128; kc += KC) {
        __syncthreads();
#pragma unroll
        for (int ii = 0; ii < 4; ii++) {
            int slot = tid + ii * 256;       // 0..1023
            int m = slot >> 3, k4 = slot & 7;
            float4 v = A4[(size_t)(m0 + m) * 32 + (kc >> 2) + k4];
            As[k4 * 4 + 0][m] = v.x;
            As[k4 * 4 + 1][m] = v.y;
            As[k4 * 4 + 2][m] = v.z;
            As[k4 * 4 + 3][m] = v.w;
        }
#pragma unroll
        for (int ii = 0; ii < 4; ii++) {
            int slot = tid + ii * 256;
            int k = slot >> 5, n4 = slot & 31;
            float4 v = B4[(size_t)(kc + k) * 256 + (n0 >> 2) + n4];
            *((float4*)&Bs[k][n4 * 4]) = v;
        }
        __syncthreads();
#pragma unroll
        for (int k = 0; k < KC; k++) {
            // vectorized LDS.128 operand reads
            float4 af0 = *(const float4*)&As[k][tm * 8];
            float4 af1 = *(const float4*)&As[k][tm * 8 + 4];
            float4 bf0 = *(const float4*)&Bs[k][tn * 8];
            float4 bf1 = *(const float4*)&Bs[k][tn * 8 + 4];
            float af[8] = {af0.x, af0.y, af0.z, af0.w, af1.x, af1.y, af1.z, af1.w};
            float bf[8] = {bf0.x, bf0.y, bf0.z, bf0.w, bf1.x, bf1.y, bf1.z, bf1.w};
#pragma unroll
            for (int mi = 0; mi < 8; mi++)
#pragma unroll
                for (int ni = 0; ni < 8; ni++) acc[mi][ni] += af[mi] * bf[ni];
        }
    }

    // epilogue: store tile + per-row sumsq
#pragma unroll
    for (int mi = 0; mi < 8; mi++) {
        int row = m0 + tm * 8 + mi;
        float rs = 0.f;
#pragma unroll
        for (int ni = 0; ni < 8; ni++) rs += acc[mi][ni] * acc[mi][ni];
        float4 v0 = make_float4(acc[mi][0], acc[mi][1], acc[mi][2], acc[mi][3]);
        float4 v1 = make_float4(acc[mi][4], acc[mi][5], acc[mi][6], acc[mi][7]);
        float4* dst = (float4*)&g_xc[(size_t)row * 1024 + n0 + tn * 8];
        dst[0] = v0;
        dst[1] = v1;
        atomicAdd(&rowred[tm * 8 + mi], rs);
    }
    __syncthreads();
    if (tid < 128) atomicAdd(&g_cs2[m0 + tid], rowred[tid]);
}

// ---------------- c factors ----------------
__global__ void k_fc() {
    int r = blockIdx.x * 256 + threadIdx.x;
    if (r >= BF_) return;
    float nxc = sqrtf(g_cs2[r]);
    float nsp = g_nsp[r];
    g_fc[r] = fminf(nxc, nsp) / (nxc + EPS);
}

// ---------------- window + overlap-add ----------------
__global__ void k_ola(float* __restrict__ out) {
    size_t idx = (size_t)blockIdx.x * 256 + threadIdx.x;  // 32 * 524288 total
    int b = (int)(idx >> 19);
    int i = (int)(idx & 524287);
    int f1 = i >> 9, j1 = i & 511;
    float c = __cosf((float)j1 * 6.13592315154256491e-3f);  // 2*pi/1024
    float w1 = 0.5f * (1.0f - c);
    float w0 = 0.5f * (1.0f + c);
    int r1 = (f1 << 5) + b;
    float v = (g_fc[r1] * g_xc[(size_t)r1 * 1024 + j1] + g_yd[(size_t)r1 * 1024 + j1]) * w1;
    if (f1 > 0) {
        int r0 = r1 - 32;
        int j0 = j1 + 512;
        v += (g_fc[r0] * g_xc[(size_t)r0 * 1024 + j0] + g_yd[(size_t)r0 * 1024 + j0]) * w0;
    }
    out[idx] = v;
}

extern "C" void kernel_launch(void* const* d_in, const int* in_sizes, int n_in,
                              void* d_out, int out_size) {
    const float* control  = (const float*)d_in[0];
    const float* proj_w   = (const float*)d_in[1];
    const float* state_m  = (const float*)d_in[2];
    const float* input_m  = (const float*)d_in[3];
    const float* output_m = (const float*)d_in[4];
    const float* direct_m = (const float*)d_in[5];
    float* out = (float*)d_out;

    k_zero<<<132, 256>>>();
    k_wd<<<128, 256>>>(proj_w, direct_m);
    k_wb<<<16, 256>>>(proj_w, input_m);
    k_gram<<<16, 256>>>(proj_w);
    k_rows<<<148, 256>>>(control);
    k_scan<<<32, 512>>>(state_m);
    k_gemm<<<dim3(8, 256), 256>>>(output_m);
    k_fc<<<128, 256>>>();
    k_ola<<<65536, 256>>>(out);
}

// round 6
// speedup vs baseline: 1.1135x; 1.0171x over previous
#include <cuda_runtime.h>
#include <math.h>

#define EPS 1e-8f
#define B_   32
#define CPD_ 32
#define F_   1024
#define D_   1024
#define S_   128
#define BF_  (B_*F_)        // 32768

typedef unsigned long long u64;

// ---------------- device scratch ----------------
__device__ float g_WD[CPD_*D_];        // W @ direct   [32][1024]
__device__ float g_WB[CPD_*S_];        // W @ input    [32][128]
__device__ float g_G[CPD_*CPD_];       // W @ W^T      [32][32]
__device__ float g_yd[(size_t)BF_*D_]; // scaled d rows [f*32+b][1024]
__device__ float g_yb[(size_t)BF_*S_]; // scaled b rows [f*32+b][128]
__device__ float g_nb2[BF_];           // ||b||^2 per frame
__device__ float g_sp[(size_t)BF_*S_]; // s'_t rows [t*32+b][128]
__device__ float g_nsp[BF_];           // ||s'_t||
__device__ float g_xc[(size_t)BF_*D_]; // unscaled c GEMM out
__device__ float g_cs2[BF_];           // row sumsq of g_xc (atomic)
__device__ float g_fc[BF_];            // c factor

// ---------------- f32x2 helpers (sm_103a packed FMA) ----------------
__device__ __forceinline__ void fma2(u64 &acc, u64 a, u64 b) {
    asm("fma.rn.f32x2 %0, %1, %2, %0;" : "+l"(acc) : "l"(a), "l"(b));
}
__device__ __forceinline__ u64 pk2(float lo, float hi) {
    u64 r; asm("mov.b64 %0, {%1, %2};" : "=l"(r) : "f"(lo), "f"(hi)); return r;
}
__device__ __forceinline__ float2 upk2(u64 v) {
    float lo, hi; asm("mov.b64 {%0, %1}, %2;" : "=f"(lo), "=f"(hi) : "l"(v));
    return make_float2(lo, hi);
}

__device__ __forceinline__ float warp_sum(float v) {
#pragma unroll
    for (int m = 16; m > 0; m >>= 1) v += __shfl_xor_sync(0xffffffffu, v, m);
    return v;
}
// two interleaved (independent) butterfly chains — ~same latency as one
__device__ __forceinline__ void warp_sum2(float &a, float &b) {
#pragma unroll
    for (int m = 16; m > 0; m >>= 1) {
        a += __shfl_xor_sync(0xffffffffu, a, m);
        b += __shfl_xor_sync(0xffffffffu, b, m);
    }
}
__device__ __forceinline__ float sqrt_pos(float x) {  // sqrt via MUFU, 0-safe
    return x * rsqrtf(fmaxf(x, 1e-30f));
}

// ---------------- prep: WD, WB, Gram, zero cs2 (fused; all independent) ----------------
__global__ __launch_bounds__(256) void k_prep(const float* __restrict__ W,
                                              const float* __restrict__ Dm,
                                              const float* __restrict__ In) {
    int bx = blockIdx.x, tid = threadIdx.x;
    if (bx < 128) {                       // WD = W @ direct
        int gid = bx * 256 + tid;
        int i = gid >> 10, j = gid & 1023;
        const float* wr = W + i * 1024;
        float a0 = 0.f, a1 = 0.f, a2 = 0.f, a3 = 0.f;
#pragma unroll 4
        for (int k = 0; k < 1024; k += 4) {
            a0 += wr[k + 0] * Dm[(k + 0) * D_ + j];
            a1 += wr[k + 1] * Dm[(k + 1) * D_ + j];
            a2 += wr[k + 2] * Dm[(k + 2) * D_ + j];
            a3 += wr[k + 3] * Dm[(k + 3) * D_ + j];
        }
        g_WD[gid] = (a0 + a1) + (a2 + a3);
    } else if (bx < 144) {                // WB = W @ input
        int gid = (bx - 128) * 256 + tid;
        int i = gid >> 7, j = gid & 127;
        const float* wr = W + i * 1024;
        float a0 = 0.f, a1 = 0.f, a2 = 0.f, a3 = 0.f;
#pragma unroll 4
        for (int k = 0; k < 1024; k += 4) {
            a0 += wr[k + 0] * In[(k + 0) * S_ + j];
            a1 += wr[k + 1] * In[(k + 1) * S_ + j];
            a2 += wr[k + 2] * In[(k + 2) * S_ + j];
            a3 += wr[k + 3] * In[(k + 3) * S_ + j];
        }
        g_WB[gid] = (a0 + a1) + (a2 + a3);
    } else if (bx == 144) {               // G = W @ W^T, single block, no atomics
        __shared__ float Wt[64 * 33];
        float acc[4] = {0.f, 0.f, 0.f, 0.f};
        for (int k0 = 0; k0 < 1024; k0 += 64) {
            __syncthreads();
            for (int lin = tid; lin < 2048; lin += 256) {
                int i = lin >> 6, kk = lin & 63;
                Wt[kk * 33 + i] = W[i * 1024 + k0 + kk];
            }
            __syncthreads();
#pragma unroll
            for (int q = 0; q < 4; q++) {
                int o = tid * 4 + q;
                int i = o >> 5, i2 = o & 31;
                float a = 0.f;
#pragma unroll 8
                for (int kk = 0; kk < 64; kk++) a += Wt[kk * 33 + i] * Wt[kk * 33 + i2];
                acc[q] += a;
            }
        }
#pragma unroll
        for (int q = 0; q < 4; q++) g_G[tid * 4 + q] = acc[q];
    } else {                              // zero g_cs2
        int base = (bx - 145) * 2048;
#pragma unroll
        for (int ii = 0; ii < 8; ii++) g_cs2[base + ii * 256 + tid] = 0.f;
    }
}

// ---------------- rows_b: yb + ||b||^2 per frame (128 threads) ----------------
__global__ __launch_bounds__(128) void k_rows_b(const float* __restrict__ control) {
    __shared__ float WBs[CPD_ * S_];
    __shared__ float Gs[CPD_ * CPD_];
    __shared__ __align__(16) float c_sh[CPD_];
    __shared__ float red_sb[4];
    __shared__ float s_nv2, s_nx2;

    int tid = threadIdx.x;
    int warp = tid >> 5, lane = tid & 31;

    for (int i = tid; i < CPD_ * S_; i += 128) WBs[i] = g_WB[i];
    for (int i = tid; i < CPD_ * CPD_; i += 128) Gs[i] = g_G[i];
    __syncthreads();

    for (int r = blockIdx.x; r < BF_; r += gridDim.x) {
        int f = r >> 5, b = r & 31;
        if (tid < 32) c_sh[tid] = control[(size_t)b * (CPD_ * F_) + tid * F_ + f];
        __syncthreads();

        if (warp == 0) {
            float ci = c_sh[lane];
            float gd = 0.f;
#pragma unroll
            for (int k = 0; k < 32; k++) gd += Gs[lane * 32 + k] * c_sh[k];
            float nv2 = ci * ci, nx2 = ci * gd;
            warp_sum2(nv2, nx2);
            if (lane == 0) { s_nv2 = nv2; s_nx2 = nx2; }
        }
        float yb = 0.f;
#pragma unroll
        for (int i = 0; i < 32; i++) yb += WBs[i * 128 + tid] * c_sh[i];
        float sb = warp_sum(yb * yb);
        if (lane == 0) red_sb[warp] = sb;
        __syncthreads();

        float tsb = (red_sb[0] + red_sb[1]) + (red_sb[2] + red_sb[3]);
        float nv = sqrt_pos(s_nv2), nx = sqrt_pos(s_nx2);
        float facp = __fdividef(fminf(nx, nv), nx + EPS);
        float nproj = facp * nx;
        float nxb = facp * sqrt_pos(tsb);
        float fb = facp * __fdividef(fminf(nxb, nproj), nxb + EPS);

        g_yb[(size_t)r * 128 + tid] = fb * yb;
        if (tid == 0) g_nb2[r] = fb * fb * tsb;
    }
}

// ---------------- rows_d: yd (256 threads, f32x2 matvec) ----------------
__global__ __launch_bounds__(256) void k_rows_d(const float* __restrict__ control) {
    __shared__ float Gs[CPD_ * CPD_];
    __shared__ __align__(16) float c_sh[CPD_];
    __shared__ float red_sd[8];
    __shared__ float s_nv2, s_nx2;

    int tid = threadIdx.x;
    int warp = tid >> 5, lane = tid & 31;

    for (int i = tid; i < CPD_ * CPD_; i += 256) Gs[i] = g_G[i];

    // WD columns {tid, tid+256, tid+512, tid+768}, packed pairs along i
    u64 wpk[4][16];
#pragma unroll
    for (int jj = 0; jj < 4; jj++)
#pragma unroll
        for (int m = 0; m < 16; m++)
            wpk[jj][m] = pk2(g_WD[(2 * m) * 1024 + jj * 256 + tid],
                             g_WD[(2 * m + 1) * 1024 + jj * 256 + tid]);
    __syncthreads();

    for (int r = blockIdx.x; r < BF_; r += gridDim.x) {
        int f = r >> 5, b = r & 31;
        if (tid < 32) c_sh[tid] = control[(size_t)b * (CPD_ * F_) + tid * F_ + f];
        __syncthreads();  // #1

        if (warp == 0) {
            float ci = c_sh[lane];
            float gd = 0.f;
#pragma unroll
            for (int k = 0; k < 32; k++) gd += Gs[lane * 32 + k] * c_sh[k];
            float nv2 = ci * ci, nx2 = ci * gd;
            warp_sum2(nv2, nx2);
            if (lane == 0) { s_nv2 = nv2; s_nx2 = nx2; }
        }

        u64 acc0 = 0, acc1 = 0, acc2 = 0, acc3 = 0;
#pragma unroll
        for (int m = 0; m < 16; m++) {
            u64 c2 = *(const u64*)&c_sh[2 * m];
            fma2(acc0, wpk[0][m], c2);
            fma2(acc1, wpk[1][m], c2);
            fma2(acc2, wpk[2][m], c2);
            fma2(acc3, wpk[3][m], c2);
        }
        float2 p0 = upk2(acc0), p1 = upk2(acc1), p2 = upk2(acc2), p3 = upk2(acc3);
        float yd0 = p0.x + p0.y, yd1 = p1.x + p1.y, yd2 = p2.x + p2.y, yd3 = p3.x + p3.y;

        float sd = warp_sum(yd0 * yd0 + yd1 * yd1 + yd2 * yd2 + yd3 * yd3);
        if (lane == 0) red_sd[warp] = sd;
        __syncthreads();  // #2

        float tsd = 0.f;
#pragma unroll
        for (int w = 0; w < 8; w++) tsd += red_sd[w];
        float nv = sqrt_pos(s_nv2), nx = sqrt_pos(s_nx2);
        float facp = __fdividef(fminf(nx, nv), nx + EPS);
        float nproj = facp * nx;
        float nxd = facp * sqrt_pos(tsd);
        float fd = facp * __fdividef(fminf(nxd, nproj), nxd + EPS);

        size_t base = (size_t)r * 1024;
        g_yd[base + 0 * 256 + tid] = fd * yd0;
        g_yd[base + 1 * 256 + tid] = fd * yd1;
        g_yd[base + 2 * 256 + tid] = fd * yd2;
        g_yd[base + 3 * 256 + tid] = fd * yd3;
    }
}

// ---------------- sequential scan (launch #4 -> gets profiled) ----------------
// 512 threads: q = tid>>7 (k-quarter), j = tid&127. 3 bars/step.
// ||s||^2 via scalar recurrence (no second reduction); f32x2 matvec; MUFU math.
__global__ __launch_bounds__(512) void k_scan(const float* __restrict__ A) {
    __shared__ __align__(16) float s_sh[S_];
    __shared__ float part[512];
    __shared__ float red1[4], red2[4];

    int b = blockIdx.x;
    int tid = threadIdx.x;
    int q = tid >> 7, j = tid & 127;
    int warp = tid >> 5, lane = tid & 31;

    // packed A pairs along k
    u64 apk[16];
#pragma unroll
    for (int m = 0; m < 16; m++)
        apk[m] = pk2(A[(q * 32 + 2 * m) * 128 + j], A[(q * 32 + 2 * m + 1) * 128 + j]);

    if (tid < 128) s_sh[tid] = 0.f;
    float ns = 0.f;                       // ||s_t|| (replicated, tid<128)
    float binp_cur = 0.f, binp_nxt = 0.f;
    float nb2_cur = 0.f, nb2_nxt = 0.f;
    if (tid < 128) {
        binp_cur = g_yb[(size_t)b * 128 + j];
        nb2_cur = g_nb2[b];
    }
    __syncthreads();

    for (int t = 0; t < F_; t++) {
        if (tid < 128 && t + 1 < F_) {    // prefetch next frame (off critical chain)
            binp_nxt = g_yb[(size_t)((t + 1) * 32 + b) * 128 + j];
            nb2_nxt = g_nb2[(t + 1) * 32 + b];
        }

        // phase A: partial matvec (f32x2)
        u64 a0 = 0, a1 = 0, a2 = 0, a3 = 0;
#pragma unroll
        for (int m = 0; m < 16; m += 4) {
            fma2(a0, apk[m + 0], *(const u64*)&s_sh[q * 32 + 2 * m + 0]);
            fma2(a1, apk[m + 1], *(const u64*)&s_sh[q * 32 + 2 * m + 2]);
            fma2(a2, apk[m + 2], *(const u64*)&s_sh[q * 32 + 2 * m + 4]);
            fma2(a3, apk[m + 3], *(const u64*)&s_sh[q * 32 + 2 * m + 6]);
        }
        float2 u0 = upk2(a0), u1 = upk2(a1), u2 = upk2(a2), u3 = upk2(a3);
        part[tid] = ((u0.x + u0.y) + (u1.x + u1.y)) + ((u2.x + u2.y) + (u3.x + u3.y));
        __syncthreads();  // #1

        float xs = 0.f;
        if (tid < 128) {
            xs = (part[j] + part[128 + j]) + (part[256 + j] + part[384 + j]);
            float px = xs * xs, pxb = xs * binp_cur;
            warp_sum2(px, pxb);
            if (lane == 0) { red1[warp] = px; red2[warp] = pxb; }
        }
        __syncthreads();  // #2

        if (tid < 128) {
            float nxs2 = (red1[0] + red1[1]) + (red1[2] + red1[3]);
            float xb = (red2[0] + red2[1]) + (red2[2] + red2[3]);
            float nxs = sqrt_pos(nxs2);
            float fac = __fdividef(fminf(nxs, ns), nxs + EPS);
            float sp = fac * xs;
            g_sp[(size_t)(t * 32 + b) * 128 + j] = sp;
            if (tid == 0) g_nsp[t * 32 + b] = fac * nxs;
            s_sh[j] = sp + binp_cur;
            // ||s_{t+1}||^2 = fac^2 ||x||^2 + 2 fac (x.b) + ||b||^2  (all scalars)
            float ns2 = fac * fac * nxs2 + 2.f * fac * xb + nb2_cur;
            ns = sqrt_pos(ns2);
            binp_cur = binp_nxt;
            nb2_cur = nb2_nxt;
        }
        __syncthreads();  // #3
    }
}

// ---------------- XC = Sprime[32768,128] @ output[128,1024], f32x2 mainloop ----------------
#define KC 32
__global__ __launch_bounds__(256) void k_gemm(const float* __restrict__ Bm) {
    __shared__ float As[KC][128];
    __shared__ float Bs[KC][128];
    __shared__ float rowred[128];

    int m0 = blockIdx.y * 128, n0 = blockIdx.x * 128;
    int tid = threadIdx.x;
    int tm = tid >> 4, tn = tid & 15;

    u64 acc2[8][4];
#pragma unroll
    for (int i = 0; i < 8; i++)
#pragma unroll
        for (int p = 0; p < 4; p++) acc2[i][p] = 0;
    if (tid < 128) rowred[tid] = 0.f;

    const float4* A4 = (const float4*)g_sp;
    const float4* B4 = (const float4*)Bm;

    for (int kc = 0; kc < 128; kc += KC) {
        __syncthreads();
#pragma unroll
        for (int ii = 0; ii < 4; ii++) {
            int slot = tid + ii * 256;
            int m = slot >> 3, k4 = slot & 7;
            float4 v = A4[(size_t)(m0 + m) * 32 + (kc >> 2) + k4];
            As[k4 * 4 + 0][m] = v.x;
            As[k4 * 4 + 1][m] = v.y;
            As[k4 * 4 + 2][m] = v.z;
            As[k4 * 4 + 3][m] = v.w;
        }
#pragma unroll
        for (int ii = 0; ii < 4; ii++) {
            int slot = tid + ii * 256;
            int k = slot >> 5, n4 = slot & 31;
            float4 v = B4[(size_t)(kc + k) * 256 + (n0 >> 2) + n4];
            *((float4*)&Bs[k][n4 * 4]) = v;
        }
        __syncthreads();
#pragma unroll
        for (int k = 0; k < KC; k++) {
            float4 af0 = *(const float4*)&As[k][tm * 8];
            float4 af1 = *(const float4*)&As[k][tm * 8 + 4];
            u64 bp0 = *(const u64*)&Bs[k][tn * 8 + 0];
            u64 bp1 = *(const u64*)&Bs[k][tn * 8 + 2];
            u64 bp2 = *(const u64*)&Bs[k][tn * 8 + 4];
            u64 bp3 = *(const u64*)&Bs[k][tn * 8 + 6];
            u64 ad[8];
            ad[0] = pk2(af0.x, af0.x); ad[1] = pk2(af0.y, af0.y);
            ad[2] = pk2(af0.z, af0.z); ad[3] = pk2(af0.w, af0.w);
            ad[4] = pk2(af1.x, af1.x); ad[5] = pk2(af1.y, af1.y);
            ad[6] = pk2(af1.z, af1.z); ad[7] = pk2(af1.w, af1.w);
#pragma unroll
            for (int mi = 0; mi < 8; mi++) {
                fma2(acc2[mi][0], ad[mi], bp0);
                fma2(acc2[mi][1], ad[mi], bp1);
                fma2(acc2[mi][2], ad[mi], bp2);
                fma2(acc2[mi][3], ad[mi], bp3);
            }
        }
    }

#pragma unroll
    for (int mi = 0; mi < 8; mi++) {
        int row = m0 + tm * 8 + mi;
        float2 c0 = upk2(acc2[mi][0]), c1 = upk2(acc2[mi][1]);
        float2 c2 = upk2(acc2[mi][2]), c3 = upk2(acc2[mi][3]);
        float rs = c0.x * c0.x + c0.y * c0.y + c1.x * c1.x + c1.y * c1.y
                 + c2.x * c2.x + c2.y * c2.y + c3.x * c3.x + c3.y * c3.y;
        float4 v0 = make_float4(c0.x, c0.y, c1.x, c1.y);
        float4 v1 = make_float4(c2.x, c2.y, c3.x, c3.y);
        float4* dst = (float4*)&g_xc[(size_t)row * 1024 + n0 + tn * 8];
        dst[0] = v0;
        dst[1] = v1;
        atomicAdd(&rowred[tm * 8 + mi], rs);
    }
    __syncthreads();
    if (tid < 128) atomicAdd(&g_cs2[m0 + tid], rowred[tid]);
}

// ---------------- c factors ----------------
__global__ void k_fc() {
    int r = blockIdx.x * 256 + threadIdx.x;
    if (r >= BF_) return;
    float nxc = sqrt_pos(g_cs2[r]);
    g_fc[r] = __fdividef(fminf(nxc, g_nsp[r]), nxc + EPS);
}

// ---------------- window + overlap-add ----------------
__global__ void k_ola(float* __restrict__ out) {
    size_t idx = (size_t)blockIdx.x * 256 + threadIdx.x;
    int b = (int)(idx >> 19);
    int i = (int)(idx & 524287);
    int f1 = i >> 9, j1 = i & 511;
    float c = __cosf((float)j1 * 6.13592315154256491e-3f);  // 2*pi/1024
    float w1 = 0.5f * (1.0f - c);
    float w0 = 0.5f * (1.0f + c);
    int r1 = (f1 << 5) + b;
    float v = (g_fc[r1] * g_xc[(size_t)r1 * 1024 + j1] + g_yd[(size_t)r1 * 1024 + j1]) * w1;
    if (f1 > 0) {
        int r0 = r1 - 32;
        int j0 = j1 + 512;
        v += (g_fc[r0] * g_xc[(size_t)r0 * 1024 + j0] + g_yd[(size_t)r0 * 1024 + j0]) * w0;
    }
    out[idx] = v;
}

extern "C" void kernel_launch(void* const* d_in, const int* in_sizes, int n_in,
                              void* d_out, int out_size) {
    const float* control  = (const float*)d_in[0];
    const float* proj_w   = (const float*)d_in[1];
    const float* state_m  = (const float*)d_in[2];
    const float* input_m  = (const float*)d_in[3];
    const float* output_m = (const float*)d_in[4];
    const float* direct_m = (const float*)d_in[5];
    float* out = (float*)d_out;

    k_prep<<<161, 256>>>(proj_w, direct_m, input_m);   // #1
    k_rows_b<<<296, 128>>>(control);                   // #2
    k_rows_d<<<148, 256>>>(control);                   // #3
    k_scan<<<32, 512>>>(state_m);                      // #4  <- profiled
    k_gemm<<<dim3(8, 256), 256>>>(output_m);           // #5
    k_fc<<<128, 256>>>();                              // #6
    k_ola<<<65536, 256>>>(out);                        // #7
}

// round 7
// speedup vs baseline: 1.1638x; 1.0452x over previous
#include <cuda_runtime.h>
#include <math.h>

#define EPS 1e-8f
#define B_   32
#define CPD_ 32
#define F_   1024
#define D_   1024
#define S_   128
#define BF_  (B_*F_)        // 32768

typedef unsigned long long u64;

// ---------------- device scratch ----------------
__device__ float g_WD[CPD_*D_];        // W @ direct   [32][1024]
__device__ float g_WB[CPD_*S_];        // W @ input    [32][128]
__device__ float g_G[CPD_*CPD_];       // W @ W^T      [32][32]
__device__ float g_yd[(size_t)BF_*D_]; // scaled d rows [f*32+b][1024]
__device__ float g_yb[(size_t)BF_*S_]; // scaled b rows [f*32+b][128]
__device__ float g_ab[(size_t)BF_*S_]; // (A^T-applied) b rows: yb @ M  [f*32+b][128]
__device__ float g_nb2[BF_];           // ||b||^2 per frame
__device__ float g_sp[(size_t)BF_*S_]; // s'_t rows [t*32+b][128]
__device__ float g_nsp[BF_];           // ||s'_t||
__device__ float g_xc[(size_t)BF_*D_]; // unscaled c GEMM out
__device__ float g_cs2[BF_];           // row sumsq of g_xc (atomic)
__device__ float g_fc[BF_];            // c factor

// ---------------- f32x2 helpers (sm_103a packed FMA) ----------------
__device__ __forceinline__ void fma2(u64 &acc, u64 a, u64 b) {
    asm("fma.rn.f32x2 %0, %1, %2, %0;" : "+l"(acc) : "l"(a), "l"(b));
}
__device__ __forceinline__ u64 pk2(float lo, float hi) {
    u64 r; asm("mov.b64 %0, {%1, %2};" : "=l"(r) : "f"(lo), "f"(hi)); return r;
}
__device__ __forceinline__ float2 upk2(u64 v) {
    float lo, hi; asm("mov.b64 {%0, %1}, %2;" : "=f"(lo), "=f"(hi) : "l"(v));
    return make_float2(lo, hi);
}

__device__ __forceinline__ float warp_sum(float v) {
#pragma unroll
    for (int m = 16; m > 0; m >>= 1) v += __shfl_xor_sync(0xffffffffu, v, m);
    return v;
}
__device__ __forceinline__ void warp_sum2(float &a, float &b) {
#pragma unroll
    for (int m = 16; m > 0; m >>= 1) {
        a += __shfl_xor_sync(0xffffffffu, a, m);
        b += __shfl_xor_sync(0xffffffffu, b, m);
    }
}
__device__ __forceinline__ float sqrt_pos(float x) {  // sqrt via MUFU, 0-safe
    return x * rsqrtf(fmaxf(x, 1e-30f));
}

// ---------------- prep: WD, WB, Gram, zero cs2 ----------------
__global__ __launch_bounds__(256) void k_prep(const float* __restrict__ W,
                                              const float* __restrict__ Dm,
                                              const float* __restrict__ In) {
    int bx = blockIdx.x, tid = threadIdx.x;
    if (bx < 128) {                       // WD = W @ direct
        int gid = bx * 256 + tid;
        int i = gid >> 10, j = gid & 1023;
        const float* wr = W + i * 1024;
        float a0 = 0.f, a1 = 0.f, a2 = 0.f, a3 = 0.f;
#pragma unroll 4
        for (int k = 0; k < 1024; k += 4) {
            a0 += wr[k + 0] * Dm[(k + 0) * D_ + j];
            a1 += wr[k + 1] * Dm[(k + 1) * D_ + j];
            a2 += wr[k + 2] * Dm[(k + 2) * D_ + j];
            a3 += wr[k + 3] * Dm[(k + 3) * D_ + j];
        }
        g_WD[gid] = (a0 + a1) + (a2 + a3);
    } else if (bx < 144) {                // WB = W @ input
        int gid = (bx - 128) * 256 + tid;
        int i = gid >> 7, j = gid & 127;
        const float* wr = W + i * 1024;
        float a0 = 0.f, a1 = 0.f, a2 = 0.f, a3 = 0.f;
#pragma unroll 4
        for (int k = 0; k < 1024; k += 4) {
            a0 += wr[k + 0] * In[(k + 0) * S_ + j];
            a1 += wr[k + 1] * In[(k + 1) * S_ + j];
            a2 += wr[k + 2] * In[(k + 2) * S_ + j];
            a3 += wr[k + 3] * In[(k + 3) * S_ + j];
        }
        g_WB[gid] = (a0 + a1) + (a2 + a3);
    } else if (bx == 144) {               // G = W @ W^T
        __shared__ float Wt[64 * 33];
        float acc[4] = {0.f, 0.f, 0.f, 0.f};
        for (int k0 = 0; k0 < 1024; k0 += 64) {
            __syncthreads();
            for (int lin = tid; lin < 2048; lin += 256) {
                int i = lin >> 6, kk = lin & 63;
                Wt[kk * 33 + i] = W[i * 1024 + k0 + kk];
            }
            __syncthreads();
#pragma unroll
            for (int q = 0; q < 4; q++) {
                int o = tid * 4 + q;
                int i = o >> 5, i2 = o & 31;
                float a = 0.f;
#pragma unroll 8
                for (int kk = 0; kk < 64; kk++) a += Wt[kk * 33 + i] * Wt[kk * 33 + i2];
                acc[q] += a;
            }
        }
#pragma unroll
        for (int q = 0; q < 4; q++) g_G[tid * 4 + q] = acc[q];
    } else {                              // zero g_cs2
        int base = (bx - 145) * 2048;
#pragma unroll
        for (int ii = 0; ii < 8; ii++) g_cs2[base + ii * 256 + tid] = 0.f;
    }
}

// ---------------- rows_b: yb + ||b||^2 per frame (128 threads) ----------------
__global__ __launch_bounds__(128) void k_rows_b(const float* __restrict__ control) {
    __shared__ float WBs[CPD_ * S_];
    __shared__ float Gs[CPD_ * CPD_];
    __shared__ __align__(16) float c_sh[CPD_];
    __shared__ float red_sb[4];
    __shared__ float s_nv2, s_nx2;

    int tid = threadIdx.x;
    int warp = tid >> 5, lane = tid & 31;

    for (int i = tid; i < CPD_ * S_; i += 128) WBs[i] = g_WB[i];
    for (int i = tid; i < CPD_ * CPD_; i += 128) Gs[i] = g_G[i];
    __syncthreads();

    for (int r = blockIdx.x; r < BF_; r += gridDim.x) {
        int f = r >> 5, b = r & 31;
        if (tid < 32) c_sh[tid] = control[(size_t)b * (CPD_ * F_) + tid * F_ + f];
        __syncthreads();

        if (warp == 0) {
            float ci = c_sh[lane];
            float gd = 0.f;
#pragma unroll
            for (int k = 0; k < 32; k++) gd += Gs[lane * 32 + k] * c_sh[k];
            float nv2 = ci * ci, nx2 = ci * gd;
            warp_sum2(nv2, nx2);
            if (lane == 0) { s_nv2 = nv2; s_nx2 = nx2; }
        }
        float yb = 0.f;
#pragma unroll
        for (int i = 0; i < 32; i++) yb += WBs[i * 128 + tid] * c_sh[i];
        float sb = warp_sum(yb * yb);
        if (lane == 0) red_sb[warp] = sb;
        __syncthreads();

        float tsb = (red_sb[0] + red_sb[1]) + (red_sb[2] + red_sb[3]);
        float nv = sqrt_pos(s_nv2), nx = sqrt_pos(s_nx2);
        float facp = __fdividef(fminf(nx, nv), nx + EPS);
        float nproj = facp * nx;
        float nxb = facp * sqrt_pos(tsb);
        float fb = facp * __fdividef(fminf(nxb, nproj), nxb + EPS);

        g_yb[(size_t)r * 128 + tid] = fb * yb;
        if (tid == 0) g_nb2[r] = fb * fb * tsb;
    }
}

// ---------------- AB = yb[32768,128] @ M[128,128]  (ab[r][j] = sum_k yb[r][k] M[k][j]) ----------------
#define KC 32
__global__ __launch_bounds__(256) void k_ab(const float* __restrict__ M) {
    __shared__ float As[KC][128];
    __shared__ float Bs[KC][128];

    int m0 = blockIdx.x * 128;
    int tid = threadIdx.x;
    int tm = tid >> 4, tn = tid & 15;

    u64 acc2[8][4];
#pragma unroll
    for (int i = 0; i < 8; i++)
#pragma unroll
        for (int p = 0; p < 4; p++) acc2[i][p] = 0;

    const float4* A4 = (const float4*)g_yb;   // rows of 32 float4
    const float4* B4 = (const float4*)M;      // rows of 32 float4

    for (int kc = 0; kc < 128; kc += KC) {
        __syncthreads();
#pragma unroll
        for (int ii = 0; ii < 4; ii++) {
            int slot = tid + ii * 256;
            int m = slot >> 3, k4 = slot & 7;
            float4 v = A4[(size_t)(m0 + m) * 32 + (kc >> 2) + k4];
            As[k4 * 4 + 0][m] = v.x;
            As[k4 * 4 + 1][m] = v.y;
            As[k4 * 4 + 2][m] = v.z;
            As[k4 * 4 + 3][m] = v.w;
        }
#pragma unroll
        for (int ii = 0; ii < 4; ii++) {
            int slot = tid + ii * 256;
            int k = slot >> 5, n4 = slot & 31;
            float4 v = B4[(size_t)(kc + k) * 32 + n4];
            *((float4*)&Bs[k][n4 * 4]) = v;
        }
        __syncthreads();
#pragma unroll
        for (int k = 0; k < KC; k++) {
            float4 af0 = *(const float4*)&As[k][tm * 8];
            float4 af1 = *(const float4*)&As[k][tm * 8 + 4];
            u64 bp0 = *(const u64*)&Bs[k][tn * 8 + 0];
            u64 bp1 = *(const u64*)&Bs[k][tn * 8 + 2];
            u64 bp2 = *(const u64*)&Bs[k][tn * 8 + 4];
            u64 bp3 = *(const u64*)&Bs[k][tn * 8 + 6];
            u64 ad[8];
            ad[0] = pk2(af0.x, af0.x); ad[1] = pk2(af0.y, af0.y);
            ad[2] = pk2(af0.z, af0.z); ad[3] = pk2(af0.w, af0.w);
            ad[4] = pk2(af1.x, af1.x); ad[5] = pk2(af1.y, af1.y);
            ad[6] = pk2(af1.z, af1.z); ad[7] = pk2(af1.w, af1.w);
#pragma unroll
            for (int mi = 0; mi < 8; mi++) {
                fma2(acc2[mi][0], ad[mi], bp0);
                fma2(acc2[mi][1], ad[mi], bp1);
                fma2(acc2[mi][2], ad[mi], bp2);
                fma2(acc2[mi][3], ad[mi], bp3);
            }
        }
    }
#pragma unroll
    for (int mi = 0; mi < 8; mi++) {
        int row = m0 + tm * 8 + mi;
        float2 c0 = upk2(acc2[mi][0]), c1 = upk2(acc2[mi][1]);
        float2 c2 = upk2(acc2[mi][2]), c3 = upk2(acc2[mi][3]);
        float4* dst = (float4*)&g_ab[(size_t)row * 128 + tn * 8];
        dst[0] = make_float4(c0.x, c0.y, c1.x, c1.y);
        dst[1] = make_float4(c2.x, c2.y, c3.x, c3.y);
    }
}

// ---------------- sequential scan, transformed recurrence ----------------
// x_t = A s_t.  x_{t+1} = fac_t*(A x_t) + ab_t ;  s'_t = fac_t x_t
// 256 threads: half = tid>>7 (k half), j = tid&127. 2 barriers/step.
// matvec (all 8 warps) overlaps the ||x||^2 / x.b reductions (lower 4 warps).
__global__ __launch_bounds__(256) void k_scan(const float* __restrict__ M) {
    __shared__ __align__(16) float x_sh[S_];
    __shared__ float part[256];
    __shared__ float red1[4], red2[4];

    int b = blockIdx.x;
    int tid = threadIdx.x;
    int half = tid >> 7, j = tid & 127;
    int warp = tid >> 5, lane = tid & 31;

    // A slice: this thread covers k in [half*64, half*64+64) for output j; M[k][j]
    u64 apk[32];
#pragma unroll
    for (int m = 0; m < 32; m++)
        apk[m] = pk2(M[(half * 64 + 2 * m) * 128 + j],
                     M[(half * 64 + 2 * m + 1) * 128 + j]);

    if (tid < 128) x_sh[tid] = 0.f;
    float x = 0.f;     // x_t[j] (register, tid<128)
    float ns = 0.f;    // ||s_t||
    float yb_cur = 0.f, ab_cur = 0.f, nb2_cur = 0.f;
    float yb_nxt = 0.f, ab_nxt = 0.f, nb2_nxt = 0.f;
    if (tid < 128) {
        yb_cur  = g_yb[(size_t)b * 128 + j];
        ab_cur  = g_ab[(size_t)b * 128 + j];
        nb2_cur = g_nb2[b];
    }
    __syncthreads();

    for (int t = 0; t < F_; t++) {
        if (tid < 128 && t + 1 < F_) {   // prefetch next frame
            size_t rn = (size_t)((t + 1) * 32 + b);
            yb_nxt  = g_yb[rn * 128 + j];
            ab_nxt  = g_ab[rn * 128 + j];
            nb2_nxt = g_nb2[rn];
        }

        // phase A: y-partial = A_slice . x_sh  (independent of reductions below)
        u64 a0 = 0, a1 = 0, a2 = 0, a3 = 0;
        int kb = half * 64;
#pragma unroll
        for (int m = 0; m < 32; m += 4) {
            fma2(a0, apk[m + 0], *(const u64*)&x_sh[kb + 2 * m + 0]);
            fma2(a1, apk[m + 1], *(const u64*)&x_sh[kb + 2 * m + 2]);
            fma2(a2, apk[m + 2], *(const u64*)&x_sh[kb + 2 * m + 4]);
            fma2(a3, apk[m + 3], *(const u64*)&x_sh[kb + 2 * m + 6]);
        }
        float2 u0 = upk2(a0), u1 = upk2(a1), u2 = upk2(a2), u3 = upk2(a3);
        part[tid] = ((u0.x + u0.y) + (u1.x + u1.y)) + ((u2.x + u2.y) + (u3.x + u3.y));

        // concurrent reductions on lower 4 warps (x in registers)
        if (tid < 128) {
            float px = x * x, pxb = x * yb_cur;
            warp_sum2(px, pxb);
            if (lane == 0) { red1[warp] = px; red2[warp] = pxb; }
        }
        __syncthreads();  // #1

        if (tid < 128) {
            float y = part[j] + part[128 + j];
            float nxs2 = (red1[0] + red1[1]) + (red1[2] + red1[3]);
            float xb   = (red2[0] + red2[1]) + (red2[2] + red2[3]);
            float nxs = sqrt_pos(nxs2);
            float fac = __fdividef(fminf(nxs, ns), nxs + EPS);
            g_sp[(size_t)(t * 32 + b) * 128 + j] = fac * x;   // s'_t
            if (tid == 0) g_nsp[t * 32 + b] = fac * nxs;
            float xn = fac * y + ab_cur;                      // x_{t+1}
            x_sh[j] = xn;
            x = xn;
            // ||s_{t+1}||^2 = fac^2||x||^2 + 2 fac (x.b) + ||b||^2
            ns = sqrt_pos(fac * fac * nxs2 + 2.f * fac * xb + nb2_cur);
            yb_cur = yb_nxt; ab_cur = ab_nxt; nb2_cur = nb2_nxt;
        }
        __syncthreads();  // #2
    }
}

// ---------------- rows_d: yd (256 threads, f32x2 matvec) ----------------
__global__ __launch_bounds__(256) void k_rows_d(const float* __restrict__ control) {
    __shared__ float Gs[CPD_ * CPD_];
    __shared__ __align__(16) float c_sh[CPD_];
    __shared__ float red_sd[8];
    __shared__ float s_nv2, s_nx2;

    int tid = threadIdx.x;
    int warp = tid >> 5, lane = tid & 31;

    for (int i = tid; i < CPD_ * CPD_; i += 256) Gs[i] = g_G[i];

    u64 wpk[4][16];
#pragma unroll
    for (int jj = 0; jj < 4; jj++)
#pragma unroll
        for (int m = 0; m < 16; m++)
            wpk[jj][m] = pk2(g_WD[(2 * m) * 1024 + jj * 256 + tid],
                             g_WD[(2 * m + 1) * 1024 + jj * 256 + tid]);
    __syncthreads();

    for (int r = blockIdx.x; r < BF_; r += gridDim.x) {
        int f = r >> 5, b = r & 31;
        if (tid < 32) c_sh[tid] = control[(size_t)b * (CPD_ * F_) + tid * F_ + f];
        __syncthreads();  // #1

        if (warp == 0) {
            float ci = c_sh[lane];
            float gd = 0.f;
#pragma unroll
            for (int k = 0; k < 32; k++) gd += Gs[lane * 32 + k] * c_sh[k];
            float nv2 = ci * ci, nx2 = ci * gd;
            warp_sum2(nv2, nx2);
            if (lane == 0) { s_nv2 = nv2; s_nx2 = nx2; }
        }

        u64 acc0 = 0, acc1 = 0, acc2 = 0, acc3 = 0;
#pragma unroll
        for (int m = 0; m < 16; m++) {
            u64 c2 = *(const u64*)&c_sh[2 * m];
            fma2(acc0, wpk[0][m], c2);
            fma2(acc1, wpk[1][m], c2);
            fma2(acc2, wpk[2][m], c2);
            fma2(acc3, wpk[3][m], c2);
        }
        float2 p0 = upk2(acc0), p1 = upk2(acc1), p2 = upk2(acc2), p3 = upk2(acc3);
        float yd0 = p0.x + p0.y, yd1 = p1.x + p1.y, yd2 = p2.x + p2.y, yd3 = p3.x + p3.y;

        float sd = warp_sum(yd0 * yd0 + yd1 * yd1 + yd2 * yd2 + yd3 * yd3);
        if (lane == 0) red_sd[warp] = sd;
        __syncthreads();  // #2

        float tsd = 0.f;
#pragma unroll
        for (int w = 0; w < 8; w++) tsd += red_sd[w];
        float nv = sqrt_pos(s_nv2), nx = sqrt_pos(s_nx2);
        float facp = __fdividef(fminf(nx, nv), nx + EPS);
        float nproj = facp * nx;
        float nxd = facp * sqrt_pos(tsd);
        float fd = facp * __fdividef(fminf(nxd, nproj), nxd + EPS);

        size_t base = (size_t)r * 1024;
        g_yd[base + 0 * 256 + tid] = fd * yd0;
        g_yd[base + 1 * 256 + tid] = fd * yd1;
        g_yd[base + 2 * 256 + tid] = fd * yd2;
        g_yd[base + 3 * 256 + tid] = fd * yd3;
    }
}

// ---------------- XC = Sprime[32768,128] @ output[128,1024], f32x2 mainloop ----------------
__global__ __launch_bounds__(256) void k_gemm(const float* __restrict__ Bm) {
    __shared__ float As[KC][128];
    __shared__ float Bs[KC][128];
    __shared__ float rowred[128];

    int m0 = blockIdx.y * 128, n0 = blockIdx.x * 128;
    int tid = threadIdx.x;
    int tm = tid >> 4, tn = tid & 15;

    u64 acc2[8][4];
#pragma unroll
    for (int i = 0; i < 8; i++)
#pragma unroll
        for (int p = 0; p < 4; p++) acc2[i][p] = 0;
    if (tid < 128) rowred[tid] = 0.f;

    const float4* A4 = (const float4*)g_sp;
    const float4* B4 = (const float4*)Bm;

    for (int kc = 0; kc < 128; kc += KC) {
        __syncthreads();
#pragma unroll
        for (int ii = 0; ii < 4; ii++) {
            int slot = tid + ii * 256;
            int m = slot >> 3, k4 = slot & 7;
            float4 v = A4[(size_t)(m0 + m) * 32 + (kc >> 2) + k4];
            As[k4 * 4 + 0][m] = v.x;
            As[k4 * 4 + 1][m] = v.y;
            As[k4 * 4 + 2][m] = v.z;
            As[k4 * 4 + 3][m] = v.w;
        }
#pragma unroll
        for (int ii = 0; ii < 4; ii++) {
            int slot = tid + ii * 256;
            int k = slot >> 5, n4 = slot & 31;
            float4 v = B4[(size_t)(kc + k) * 256 + (n0 >> 2) + n4];
            *((float4*)&Bs[k][n4 * 4]) = v;
        }
        __syncthreads();
#pragma unroll
        for (int k = 0; k < KC; k++) {
            float4 af0 = *(const float4*)&As[k][tm * 8];
            float4 af1 = *(const float4*)&As[k][tm * 8 + 4];
            u64 bp0 = *(const u64*)&Bs[k][tn * 8 + 0];
            u64 bp1 = *(const u64*)&Bs[k][tn * 8 + 2];
            u64 bp2 = *(const u64*)&Bs[k][tn * 8 + 4];
            u64 bp3 = *(const u64*)&Bs[k][tn * 8 + 6];
            u64 ad[8];
            ad[0] = pk2(af0.x, af0.x); ad[1] = pk2(af0.y, af0.y);
            ad[2] = pk2(af0.z, af0.z); ad[3] = pk2(af0.w, af0.w);
            ad[4] = pk2(af1.x, af1.x); ad[5] = pk2(af1.y, af1.y);
            ad[6] = pk2(af1.z, af1.z); ad[7] = pk2(af1.w, af1.w);
#pragma unroll
            for (int mi = 0; mi < 8; mi++) {
                fma2(acc2[mi][0], ad[mi], bp0);
                fma2(acc2[mi][1], ad[mi], bp1);
                fma2(acc2[mi][2], ad[mi], bp2);
                fma2(acc2[mi][3], ad[mi], bp3);
            }
        }
    }

#pragma unroll
    for (int mi = 0; mi < 8; mi++) {
        int row = m0 + tm * 8 + mi;
        float2 c0 = upk2(acc2[mi][0]), c1 = upk2(acc2[mi][1]);
        float2 c2 = upk2(acc2[mi][2]), c3 = upk2(acc2[mi][3]);
        float rs = c0.x * c0.x + c0.y * c0.y + c1.x * c1.x + c1.y * c1.y
                 + c2.x * c2.x + c2.y * c2.y + c3.x * c3.x + c3.y * c3.y;
        float4* dst = (float4*)&g_xc[(size_t)row * 1024 + n0 + tn * 8];
        dst[0] = make_float4(c0.x, c0.y, c1.x, c1.y);
        dst[1] = make_float4(c2.x, c2.y, c3.x, c3.y);
        atomicAdd(&rowred[tm * 8 + mi], rs);
    }
    __syncthreads();
    if (tid < 128) atomicAdd(&g_cs2[m0 + tid], rowred[tid]);
}

// ---------------- c factors ----------------
__global__ void k_fc() {
    int r = blockIdx.x * 256 + threadIdx.x;
    if (r >= BF_) return;
    float nxc = sqrt_pos(g_cs2[r]);
    g_fc[r] = __fdividef(fminf(nxc, g_nsp[r]), nxc + EPS);
}

// ---------------- window + overlap-add ----------------
__global__ void k_ola(float* __restrict__ out) {
    size_t idx = (size_t)blockIdx.x * 256 + threadIdx.x;
    int b = (int)(idx >> 19);
    int i = (int)(idx & 524287);
    int f1 = i >> 9, j1 = i & 511;
    float c = __cosf((float)j1 * 6.13592315154256491e-3f);  // 2*pi/1024
    float w1 = 0.5f * (1.0f - c);
    float w0 = 0.5f * (1.0f + c);
    int r1 = (f1 << 5) + b;
    float v = (g_fc[r1] * g_xc[(size_t)r1 * 1024 + j1] + g_yd[(size_t)r1 * 1024 + j1]) * w1;
    if (f1 > 0) {
        int r0 = r1 - 32;
        int j0 = j1 + 512;
        v += (g_fc[r0] * g_xc[(size_t)r0 * 1024 + j0] + g_yd[(size_t)r0 * 1024 + j0]) * w0;
    }
    out[idx] = v;
}

extern "C" void kernel_launch(void* const* d_in, const int* in_sizes, int n_in,
                              void* d_out, int out_size) {
    const float* control  = (const float*)d_in[0];
    const float* proj_w   = (const float*)d_in[1];
    const float* state_m  = (const float*)d_in[2];
    const float* input_m  = (const float*)d_in[3];
    const float* output_m = (const float*)d_in[4];
    const float* direct_m = (const float*)d_in[5];
    float* out = (float*)d_out;

    k_prep<<<161, 256>>>(proj_w, direct_m, input_m);   // #1
    k_rows_b<<<296, 128>>>(control);                   // #2
    k_ab<<<256, 256>>>(state_m);                       // #3
    k_scan<<<32, 256>>>(state_m);                      // #4  <- profiled
    k_rows_d<<<148, 256>>>(control);                   // #5
    k_gemm<<<dim3(8, 256), 256>>>(output_m);           // #6
    k_fc<<<128, 256>>>();                              // #7
    k_ola<<<65536, 256>>>(out);                        // #8
}

// round 8
// speedup vs baseline: 1.1658x; 1.0017x over previous
#include <cuda_runtime.h>
#include <math.h>

#define EPS 1e-8f
#define B_   32
#define CPD_ 32
#define F_   1024
#define D_   1024
#define S_   128
#define BF_  (B_*F_)        // 32768

typedef unsigned long long u64;

// ---------------- device scratch ----------------
__device__ float g_WD[CPD_*D_];        // W @ direct   [32][1024]
__device__ float g_WB[CPD_*S_];        // W @ input    [32][128]
__device__ float g_G[CPD_*CPD_];       // W @ W^T      [32][32]
__device__ float g_yd[(size_t)BF_*D_]; // scaled d rows [f*32+b][1024]
__device__ float g_yb[(size_t)BF_*S_]; // scaled b rows [f*32+b][128]
__device__ float g_ab[(size_t)BF_*S_]; // yb @ M  [f*32+b][128]
__device__ float g_nb2[BF_];           // ||b||^2 per frame
__device__ float g_sp[(size_t)BF_*S_]; // s'_t rows [t*32+b][128]
__device__ float g_nsp[BF_];           // ||s'_t||
__device__ float g_xc[(size_t)BF_*D_]; // unscaled c GEMM out
__device__ float g_cs2[BF_];           // row sumsq of g_xc (atomic)
__device__ float g_fc[BF_];            // c factor

// ---------------- f32x2 helpers ----------------
__device__ __forceinline__ void fma2(u64 &acc, u64 a, u64 b) {
    asm("fma.rn.f32x2 %0, %1, %2, %0;" : "+l"(acc) : "l"(a), "l"(b));
}
__device__ __forceinline__ u64 pk2(float lo, float hi) {
    u64 r; asm("mov.b64 %0, {%1, %2};" : "=l"(r) : "f"(lo), "f"(hi)); return r;
}
__device__ __forceinline__ float2 upk2(u64 v) {
    float lo, hi; asm("mov.b64 {%0, %1}, %2;" : "=f"(lo), "=f"(hi) : "l"(v));
    return make_float2(lo, hi);
}

__device__ __forceinline__ float warp_sum(float v) {
#pragma unroll
    for (int m = 16; m > 0; m >>= 1) v += __shfl_xor_sync(0xffffffffu, v, m);
    return v;
}
__device__ __forceinline__ void warp_sum2(float &a, float &b) {
#pragma unroll
    for (int m = 16; m > 0; m >>= 1) {
        a += __shfl_xor_sync(0xffffffffu, a, m);
        b += __shfl_xor_sync(0xffffffffu, b, m);
    }
}
__device__ __forceinline__ float sqrt_pos(float x) {
    return x * rsqrtf(fmaxf(x, 1e-30f));
}

// ---------------- prep: WD, WB, Gram, zero cs2 ----------------
__global__ __launch_bounds__(256) void k_prep(const float* __restrict__ W,
                                              const float* __restrict__ Dm,
                                              const float* __restrict__ In) {
    int bx = blockIdx.x, tid = threadIdx.x;
    if (bx < 128) {
        int gid = bx * 256 + tid;
        int i = gid >> 10, j = gid & 1023;
        const float* wr = W + i * 1024;
        float a0 = 0.f, a1 = 0.f, a2 = 0.f, a3 = 0.f;
#pragma unroll 4
        for (int k = 0; k < 1024; k += 4) {
            a0 += wr[k + 0] * Dm[(k + 0) * D_ + j];
            a1 += wr[k + 1] * Dm[(k + 1) * D_ + j];
            a2 += wr[k + 2] * Dm[(k + 2) * D_ + j];
            a3 += wr[k + 3] * Dm[(k + 3) * D_ + j];
        }
        g_WD[gid] = (a0 + a1) + (a2 + a3);
    } else if (bx < 144) {
        int gid = (bx - 128) * 256 + tid;
        int i = gid >> 7, j = gid & 127;
        const float* wr = W + i * 1024;
        float a0 = 0.f, a1 = 0.f, a2 = 0.f, a3 = 0.f;
#pragma unroll 4
        for (int k = 0; k < 1024; k += 4) {
            a0 += wr[k + 0] * In[(k + 0) * S_ + j];
            a1 += wr[k + 1] * In[(k + 1) * S_ + j];
            a2 += wr[k + 2] * In[(k + 2) * S_ + j];
            a3 += wr[k + 3] * In[(k + 3) * S_ + j];
        }
        g_WB[gid] = (a0 + a1) + (a2 + a3);
    } else if (bx == 144) {
        __shared__ float Wt[64 * 33];
        float acc[4] = {0.f, 0.f, 0.f, 0.f};
        for (int k0 = 0; k0 < 1024; k0 += 64) {
            __syncthreads();
            for (int lin = tid; lin < 2048; lin += 256) {
                int i = lin >> 6, kk = lin & 63;
                Wt[kk * 33 + i] = W[i * 1024 + k0 + kk];
            }
            __syncthreads();
#pragma unroll
            for (int q = 0; q < 4; q++) {
                int o = tid * 4 + q;
                int i = o >> 5, i2 = o & 31;
                float a = 0.f;
#pragma unroll 8
                for (int kk = 0; kk < 64; kk++) a += Wt[kk * 33 + i] * Wt[kk * 33 + i2];
                acc[q] += a;
            }
        }
#pragma unroll
        for (int q = 0; q < 4; q++) g_G[tid * 4 + q] = acc[q];
    } else {
        int base = (bx - 145) * 2048;
#pragma unroll
        for (int ii = 0; ii < 8; ii++) g_cs2[base + ii * 256 + tid] = 0.f;
    }
}

// ---------------- rows_b: yb + ||b||^2 per frame (128 threads) ----------------
__global__ __launch_bounds__(128) void k_rows_b(const float* __restrict__ control) {
    __shared__ float WBs[CPD_ * S_];
    __shared__ float Gs[CPD_ * CPD_];
    __shared__ __align__(16) float c_sh[CPD_];
    __shared__ float red_sb[4];
    __shared__ float s_nv2, s_nx2;

    int tid = threadIdx.x;
    int warp = tid >> 5, lane = tid & 31;

    for (int i = tid; i < CPD_ * S_; i += 128) WBs[i] = g_WB[i];
    for (int i = tid; i < CPD_ * CPD_; i += 128) Gs[i] = g_G[i];
    __syncthreads();

    for (int r = blockIdx.x; r < BF_; r += gridDim.x) {
        int f = r >> 5, b = r & 31;
        if (tid < 32) c_sh[tid] = control[(size_t)b * (CPD_ * F_) + tid * F_ + f];
        __syncthreads();

        if (warp == 0) {
            float ci = c_sh[lane];
            float gd = 0.f;
#pragma unroll
            for (int k = 0; k < 32; k++) gd += Gs[lane * 32 + k] * c_sh[k];
            float nv2 = ci * ci, nx2 = ci * gd;
            warp_sum2(nv2, nx2);
            if (lane == 0) { s_nv2 = nv2; s_nx2 = nx2; }
        }
        float yb = 0.f;
#pragma unroll
        for (int i = 0; i < 32; i++) yb += WBs[i * 128 + tid] * c_sh[i];
        float sb = warp_sum(yb * yb);
        if (lane == 0) red_sb[warp] = sb;
        __syncthreads();

        float tsb = (red_sb[0] + red_sb[1]) + (red_sb[2] + red_sb[3]);
        float nv = sqrt_pos(s_nv2), nx = sqrt_pos(s_nx2);
        float facp = __fdividef(fminf(nx, nv), nx + EPS);
        float nproj = facp * nx;
        float nxb = facp * sqrt_pos(tsb);
        float fb = facp * __fdividef(fminf(nxb, nproj), nxb + EPS);

        g_yb[(size_t)r * 128 + tid] = fb * yb;
        if (tid == 0) g_nb2[r] = fb * fb * tsb;
    }
}

// ---------------- AB = yb[32768,128] @ M[128,128] ----------------
#define KC 32
__global__ __launch_bounds__(256) void k_ab(const float* __restrict__ M) {
    __shared__ float As[KC][128];
    __shared__ float Bs[KC][128];

    int m0 = blockIdx.x * 128;
    int tid = threadIdx.x;
    int tm = tid >> 4, tn = tid & 15;

    u64 acc2[8][4];
#pragma unroll
    for (int i = 0; i < 8; i++)
#pragma unroll
        for (int p = 0; p < 4; p++) acc2[i][p] = 0;

    const float4* A4 = (const float4*)g_yb;
    const float4* B4 = (const float4*)M;

    for (int kc = 0; kc < 128; kc += KC) {
        __syncthreads();
#pragma unroll
        for (int ii = 0; ii < 4; ii++) {
            int slot = tid + ii * 256;
            int m = slot >> 3, k4 = slot & 7;
            float4 v = A4[(size_t)(m0 + m) * 32 + (kc >> 2) + k4];
            As[k4 * 4 + 0][m] = v.x;
            As[k4 * 4 + 1][m] = v.y;
            As[k4 * 4 + 2][m] = v.z;
            As[k4 * 4 + 3][m] = v.w;
        }
#pragma unroll
        for (int ii = 0; ii < 4; ii++) {
            int slot = tid + ii * 256;
            int k = slot >> 5, n4 = slot & 31;
            float4 v = B4[(size_t)(kc + k) * 32 + n4];
            *((float4*)&Bs[k][n4 * 4]) = v;
        }
        __syncthreads();
#pragma unroll
        for (int k = 0; k < KC; k++) {
            float4 af0 = *(const float4*)&As[k][tm * 8];
            float4 af1 = *(const float4*)&As[k][tm * 8 + 4];
            u64 bp0 = *(const u64*)&Bs[k][tn * 8 + 0];
            u64 bp1 = *(const u64*)&Bs[k][tn * 8 + 2];
            u64 bp2 = *(const u64*)&Bs[k][tn * 8 + 4];
            u64 bp3 = *(const u64*)&Bs[k][tn * 8 + 6];
            u64 ad[8];
            ad[0] = pk2(af0.x, af0.x); ad[1] = pk2(af0.y, af0.y);
            ad[2] = pk2(af0.z, af0.z); ad[3] = pk2(af0.w, af0.w);
            ad[4] = pk2(af1.x, af1.x); ad[5] = pk2(af1.y, af1.y);
            ad[6] = pk2(af1.z, af1.z); ad[7] = pk2(af1.w, af1.w);
#pragma unroll
            for (int mi = 0; mi < 8; mi++) {
                fma2(acc2[mi][0], ad[mi], bp0);
                fma2(acc2[mi][1], ad[mi], bp1);
                fma2(acc2[mi][2], ad[mi], bp2);
                fma2(acc2[mi][3], ad[mi], bp3);
            }
        }
    }
#pragma unroll
    for (int mi = 0; mi < 8; mi++) {
        int row = m0 + tm * 8 + mi;
        float2 c0 = upk2(acc2[mi][0]), c1 = upk2(acc2[mi][1]);
        float2 c2 = upk2(acc2[mi][2]), c3 = upk2(acc2[mi][3]);
        float4* dst = (float4*)&g_ab[(size_t)row * 128 + tn * 8];
        dst[0] = make_float4(c0.x, c0.y, c1.x, c1.y);
        dst[1] = make_float4(c2.x, c2.y, c3.x, c3.y);
    }
}

// ---------------- sequential scan, transformed recurrence + depth-4 prefetch ring ----------------
// x_t = A s_t.  x_{t+1} = fac_t*(A x_t) + ab_t ;  s'_t = fac_t x_t
// 256 threads, 2 barriers/step. Frame inputs prefetched 4 steps ahead so the
// DRAM LDG latency (~600-1000cyc) never sits on the step critical path.
__global__ __launch_bounds__(256) void k_scan(const float* __restrict__ M) {
    __shared__ __align__(16) float x_sh[S_];
    __shared__ float part[256];
    __shared__ float red1[4], red2[4];

    int b = blockIdx.x;
    int tid = threadIdx.x;
    int half = tid >> 7, j = tid & 127;
    int warp = tid >> 5, lane = tid & 31;

    u64 apk[32];
#pragma unroll
    for (int m = 0; m < 32; m++)
        apk[m] = pk2(M[(half * 64 + 2 * m) * 128 + j],
                     M[(half * 64 + 2 * m + 1) * 128 + j]);

    if (tid < 128) x_sh[tid] = 0.f;
    float x = 0.f;     // x_t[j] (register, tid<128)
    float ns = 0.f;    // ||s_t||

    // depth-4 prefetch ring (frames t..t+3 resident)
    float ybq[4], abq[4], nb2q[4];
    if (tid < 128) {
#pragma unroll
        for (int d = 0; d < 4; d++) {
            size_t rr = (size_t)(d * 32 + b);
            ybq[d]  = g_yb[rr * 128 + j];
            abq[d]  = g_ab[rr * 128 + j];
            nb2q[d] = g_nb2[rr];
        }
    }
    __syncthreads();

#pragma unroll 1
    for (int tb = 0; tb < F_; tb += 4) {
#pragma unroll
        for (int c = 0; c < 4; c++) {
            int t = tb + c;
            // phase A: matvec partial (all 8 warps) using x_sh from prev step
            u64 a0 = 0, a1 = 0, a2 = 0, a3 = 0;
            int kb = half * 64;
#pragma unroll
            for (int m = 0; m < 32; m += 4) {
                fma2(a0, apk[m + 0], *(const u64*)&x_sh[kb + 2 * m + 0]);
                fma2(a1, apk[m + 1], *(const u64*)&x_sh[kb + 2 * m + 2]);
                fma2(a2, apk[m + 2], *(const u64*)&x_sh[kb + 2 * m + 4]);
                fma2(a3, apk[m + 3], *(const u64*)&x_sh[kb + 2 * m + 6]);
            }
            float2 u0 = upk2(a0), u1 = upk2(a1), u2 = upk2(a2), u3 = upk2(a3);
            part[tid] = ((u0.x + u0.y) + (u1.x + u1.y)) + ((u2.x + u2.y) + (u3.x + u3.y));

            // concurrent: ||x||^2 and x.b reductions (lower 4 warps, x in regs)
            if (tid < 128) {
                float px = x * x, pxb = x * ybq[c];
                warp_sum2(px, pxb);
                if (lane == 0) { red1[warp] = px; red2[warp] = pxb; }
            }
            __syncthreads();  // #1

            if (tid < 128) {
                float y = part[j] + part[128 + j];
                float nxs2 = (red1[0] + red1[1]) + (red1[2] + red1[3]);
                float xb   = (red2[0] + red2[1]) + (red2[2] + red2[3]);
                float nxs = sqrt_pos(nxs2);
                float fac = __fdividef(fminf(nxs, ns), nxs + EPS);
                g_sp[(size_t)(t * 32 + b) * 128 + j] = fac * x;
                if (tid == 0) g_nsp[t * 32 + b] = fac * nxs;
                float xn = fac * y + abq[c];
                x_sh[j] = xn;
                x = xn;
                ns = sqrt_pos(fac * fac * nxs2 + 2.f * fac * xb + nb2q[c]);

                // slot c now free: prefetch frame t+4 (lands ~3 steps later)
                if (t + 4 < F_) {
                    size_t rn = (size_t)((t + 4) * 32 + b);
                    ybq[c]  = g_yb[rn * 128 + j];
                    abq[c]  = g_ab[rn * 128 + j];
                    nb2q[c] = g_nb2[rn];
                }
            }
            __syncthreads();  // #2
        }
    }
}

// ---------------- rows_d: yd (256 threads, f32x2 matvec) ----------------
__global__ __launch_bounds__(256) void k_rows_d(const float* __restrict__ control) {
    __shared__ float Gs[CPD_ * CPD_];
    __shared__ __align__(16) float c_sh[CPD_];
    __shared__ float red_sd[8];
    __shared__ float s_nv2, s_nx2;

    int tid = threadIdx.x;
    int warp = tid >> 5, lane = tid & 31;

    for (int i = tid; i < CPD_ * CPD_; i += 256) Gs[i] = g_G[i];

    u64 wpk[4][16];
#pragma unroll
    for (int jj = 0; jj < 4; jj++)
#pragma unroll
        for (int m = 0; m < 16; m++)
            wpk[jj][m] = pk2(g_WD[(2 * m) * 1024 + jj * 256 + tid],
                             g_WD[(2 * m + 1) * 1024 + jj * 256 + tid]);
    __syncthreads();

    for (int r = blockIdx.x; r < BF_; r += gridDim.x) {
        int f = r >> 5, b = r & 31;
        if (tid < 32) c_sh[tid] = control[(size_t)b * (CPD_ * F_) + tid * F_ + f];
        __syncthreads();  // #1

        if (warp == 0) {
            float ci = c_sh[lane];
            float gd = 0.f;
#pragma unroll
            for (int k = 0; k < 32; k++) gd += Gs[lane * 32 + k] * c_sh[k];
            float nv2 = ci * ci, nx2 = ci * gd;
            warp_sum2(nv2, nx2);
            if (lane == 0) { s_nv2 = nv2; s_nx2 = nx2; }
        }

        u64 acc0 = 0, acc1 = 0, acc2 = 0, acc3 = 0;
#pragma unroll
        for (int m = 0; m < 16; m++) {
            u64 c2 = *(const u64*)&c_sh[2 * m];
            fma2(acc0, wpk[0][m], c2);
            fma2(acc1, wpk[1][m], c2);
            fma2(acc2, wpk[2][m], c2);
            fma2(acc3, wpk[3][m], c2);
        }
        float2 p0 = upk2(acc0), p1 = upk2(acc1), p2 = upk2(acc2), p3 = upk2(acc3);
        float yd0 = p0.x + p0.y, yd1 = p1.x + p1.y, yd2 = p2.x + p2.y, yd3 = p3.x + p3.y;

        float sd = warp_sum(yd0 * yd0 + yd1 * yd1 + yd2 * yd2 + yd3 * yd3);
        if (lane == 0) red_sd[warp] = sd;
        __syncthreads();  // #2

        float tsd = 0.f;
#pragma unroll
        for (int w = 0; w < 8; w++) tsd += red_sd[w];
        float nv = sqrt_pos(s_nv2), nx = sqrt_pos(s_nx2);
        float facp = __fdividef(fminf(nx, nv), nx + EPS);
        float nproj = facp * nx;
        float nxd = facp * sqrt_pos(tsd);
        float fd = facp * __fdividef(fminf(nxd, nproj), nxd + EPS);

        size_t base = (size_t)r * 1024;
        g_yd[base + 0 * 256 + tid] = fd * yd0;
        g_yd[base + 1 * 256 + tid] = fd * yd1;
        g_yd[base + 2 * 256 + tid] = fd * yd2;
        g_yd[base + 3 * 256 + tid] = fd * yd3;
    }
}

// ---------------- XC = Sprime[32768,128] @ output[128,1024] ----------------
__global__ __launch_bounds__(256) void k_gemm(const float* __restrict__ Bm) {
    __shared__ float As[KC][128];
    __shared__ float Bs[KC][128];
    __shared__ float rowred[128];

    int m0 = blockIdx.y * 128, n0 = blockIdx.x * 128;
    int tid = threadIdx.x;
    int tm = tid >> 4, tn = tid & 15;

    u64 acc2[8][4];
#pragma unroll
    for (int i = 0; i < 8; i++)
#pragma unroll
        for (int p = 0; p < 4; p++) acc2[i][p] = 0;
    if (tid < 128) rowred[tid] = 0.f;

    const float4* A4 = (const float4*)g_sp;
    const float4* B4 = (const float4*)Bm;

    for (int kc = 0; kc < 128; kc += KC) {
        __syncthreads();
#pragma unroll
        for (int ii = 0; ii < 4; ii++) {
            int slot = tid + ii * 256;
            int m = slot >> 3, k4 = slot & 7;
            float4 v = A4[(size_t)(m0 + m) * 32 + (kc >> 2) + k4];
            As[k4 * 4 + 0][m] = v.x;
            As[k4 * 4 + 1][m] = v.y;
            As[k4 * 4 + 2][m] = v.z;
            As[k4 * 4 + 3][m] = v.w;
        }
#pragma unroll
        for (int ii = 0; ii < 4; ii++) {
            int slot = tid + ii * 256;
            int k = slot >> 5, n4 = slot & 31;
            float4 v = B4[(size_t)(kc + k) * 256 + (n0 >> 2) + n4];
            *((float4*)&Bs[k][n4 * 4]) = v;
        }
        __syncthreads();
#pragma unroll
        for (int k = 0; k < KC; k++) {
            float4 af0 = *(const float4*)&As[k][tm * 8];
            float4 af1 = *(const float4*)&As[k][tm * 8 + 4];
            u64 bp0 = *(const u64*)&Bs[k][tn * 8 + 0];
            u64 bp1 = *(const u64*)&Bs[k][tn * 8 + 2];
            u64 bp2 = *(const u64*)&Bs[k][tn * 8 + 4];
            u64 bp3 = *(const u64*)&Bs[k][tn * 8 + 6];
            u64 ad[8];
            ad[0] = pk2(af0.x, af0.x); ad[1] = pk2(af0.y, af0.y);
            ad[2] = pk2(af0.z, af0.z); ad[3] = pk2(af0.w, af0.w);
            ad[4] = pk2(af1.x, af1.x); ad[5] = pk2(af1.y, af1.y);
            ad[6] = pk2(af1.z, af1.z); ad[7] = pk2(af1.w, af1.w);
#pragma unroll
            for (int mi = 0; mi < 8; mi++) {
                fma2(acc2[mi][0], ad[mi], bp0);
                fma2(acc2[mi][1], ad[mi], bp1);
                fma2(acc2[mi][2], ad[mi], bp2);
                fma2(acc2[mi][3], ad[mi], bp3);
            }
        }
    }

#pragma unroll
    for (int mi = 0; mi < 8; mi++) {
        int row = m0 + tm * 8 + mi;
        float2 c0 = upk2(acc2[mi][0]), c1 = upk2(acc2[mi][1]);
        float2 c2 = upk2(acc2[mi][2]), c3 = upk2(acc2[mi][3]);
        float rs = c0.x * c0.x + c0.y * c0.y + c1.x * c1.x + c1.y * c1.y
                 + c2.x * c2.x + c2.y * c2.y + c3.x * c3.x + c3.y * c3.y;
        float4* dst = (float4*)&g_xc[(size_t)row * 1024 + n0 + tn * 8];
        dst[0] = make_float4(c0.x, c0.y, c1.x, c1.y);
        dst[1] = make_float4(c2.x, c2.y, c3.x, c3.y);
        atomicAdd(&rowred[tm * 8 + mi], rs);
    }
    __syncthreads();
    if (tid < 128) atomicAdd(&g_cs2[m0 + tid], rowred[tid]);
}

// ---------------- c factors ----------------
__global__ void k_fc() {
    int r = blockIdx.x * 256 + threadIdx.x;
    if (r >= BF_) return;
    float nxc = sqrt_pos(g_cs2[r]);
    g_fc[r] = __fdividef(fminf(nxc, g_nsp[r]), nxc + EPS);
}

// ---------------- window + overlap-add ----------------
__global__ void k_ola(float* __restrict__ out) {
    size_t idx = (size_t)blockIdx.x * 256 + threadIdx.x;
    int b = (int)(idx >> 19);
    int i = (int)(idx & 524287);
    int f1 = i >> 9, j1 = i & 511;
    float c = __cosf((float)j1 * 6.13592315154256491e-3f);  // 2*pi/1024
    float w1 = 0.5f * (1.0f - c);
    float w0 = 0.5f * (1.0f + c);
    int r1 = (f1 << 5) + b;
    float v = (g_fc[r1] * g_xc[(size_t)r1 * 1024 + j1] + g_yd[(size_t)r1 * 1024 + j1]) * w1;
    if (f1 > 0) {
        int r0 = r1 - 32;
        int j0 = j1 + 512;
        v += (g_fc[r0] * g_xc[(size_t)r0 * 1024 + j0] + g_yd[(size_t)r0 * 1024 + j0]) * w0;
    }
    out[idx] = v;
}

extern "C" void kernel_launch(void* const* d_in, const int* in_sizes, int n_in,
                              void* d_out, int out_size) {
    const float* control  = (const float*)d_in[0];
    const float* proj_w   = (const float*)d_in[1];
    const float* state_m  = (const float*)d_in[2];
    const float* input_m  = (const float*)d_in[3];
    const float* output_m = (const float*)d_in[4];
    const float* direct_m = (const float*)d_in[5];
    float* out = (float*)d_out;

    k_prep<<<161, 256>>>(proj_w, direct_m, input_m);   // #1
    k_rows_b<<<296, 128>>>(control);                   // #2
    k_ab<<<256, 256>>>(state_m);                       // #3
    k_scan<<<32, 256>>>(state_m);                      // #4  <- profiled
    k_rows_d<<<148, 256>>>(control);                   // #5
    k_gemm<<<dim3(8, 256), 256>>>(output_m);           // #6
    k_fc<<<128, 256>>>();                              // #7
    k_ola<<<65536, 256>>>(out);                        // #8
}